// round 5
// baseline (speedup 1.0000x reference)
#include <cuda_runtime.h>
#include <math_constants.h>

#define N_SAMPLES 4096
#define D_IN      1024
#define D_OUT     256

// ---------------- persistent device scratch (no allocations allowed) --------
__device__ float g_h [N_SAMPLES * D_OUT];   // projected features, 4 MB (fits in L2)
__device__ float g_sq[N_SAMPLES];           // ||h_i||^2
__device__ float g_hp[N_SAMPLES];           // hardest positive (max dist, same class)
__device__ float g_hn[N_SAMPLES];           // hardest negative (min dist, diff class)
__device__ int   g_is64;                    // targets dtype flag

__device__ __forceinline__ int get_cls(const void* T, int i, int is64) {
    return is64 ? (int)((const long long*)T)[i] : ((const int*)T)[i];
}

// ---------------- kernel 0: dtype detect + per-launch re-init ---------------
// If targets is int64 (little-endian, values 0..63), every odd 32-bit word of
// the first 2048 elements is zero. If int32, odd words are random 0..63 and
// some are certainly nonzero. Deterministic for fixed inputs.
__global__ void k_init(const unsigned* __restrict__ twords) {
    __shared__ unsigned red[32];
    int tid = threadIdx.x;
    unsigned acc = 0;
    for (int i = tid; i < 2048; i += 1024) acc |= twords[2 * i + 1];
    #pragma unroll
    for (int o = 16; o; o >>= 1) acc |= __shfl_xor_sync(0xffffffffu, acc, o);
    if ((tid & 31) == 0) red[tid >> 5] = acc;
    __syncthreads();
    if (tid < 32) {
        unsigned v = red[tid];
        #pragma unroll
        for (int o = 16; o; o >>= 1) v |= __shfl_xor_sync(0xffffffffu, v, o);
        if (tid == 0) g_is64 = (v == 0u) ? 1 : 0;
    }
    // re-init accumulators EVERY launch (graph replays reuse device globals)
    for (int i = tid; i < N_SAMPLES; i += 1024) {
        g_hp[i] = 0.0f;            // true max >= 0 (self term), so 0 is safe
        g_hn[i] = CUDART_INF_F;
    }
}

// ---------------- kernel 1: h = x @ W + b  (4096x1024 * 1024x256) -----------
// BM=128, BN=64, BK=8, 256 threads, 8x4 micro-tile.
#define FC_BM 128
#define FC_BN 64
#define FC_BK 8

__global__ __launch_bounds__(256) void k_fc(const float* __restrict__ x,
                                            const float* __restrict__ W,
                                            const float* __restrict__ bias) {
    __shared__ __align__(16) float As[FC_BK][FC_BM + 4];  // transposed, padded
    __shared__ __align__(16) float Bs[FC_BK][FC_BN];

    int tid = threadIdx.x;
    int tx  = tid & 15;          // 16 -> n (4 cols each)
    int ty  = tid >> 4;          // 16 -> m (8 rows each)
    int m0  = blockIdx.y * FC_BM;
    int n0  = blockIdx.x * FC_BN;

    float acc[8][4];
    #pragma unroll
    for (int i = 0; i < 8; i++)
        #pragma unroll
        for (int j = 0; j < 4; j++) acc[i][j] = 0.0f;

    int am = tid >> 1;               // 0..127 : row within tile
    int ak = (tid & 1) * 4;          // 0 or 4 : k offset
    int bk = tid >> 4;               // (only tid<128 used) 0..7
    int bn = tid & 15;               // 0..15 float4 along n

    for (int k0 = 0; k0 < D_IN; k0 += FC_BK) {
        float4 av = *(const float4*)&x[(m0 + am) * D_IN + k0 + ak];
        As[ak + 0][am] = av.x; As[ak + 1][am] = av.y;
        As[ak + 2][am] = av.z; As[ak + 3][am] = av.w;
        if (tid < 128) {
            float4 bv = *(const float4*)&W[(k0 + bk) * D_OUT + n0 + bn * 4];
            *(float4*)&Bs[bk][bn * 4] = bv;
        }
        __syncthreads();
        #pragma unroll
        for (int k = 0; k < FC_BK; k++) {
            float4 a0 = *(const float4*)&As[k][ty * 8];
            float4 a1 = *(const float4*)&As[k][ty * 8 + 4];
            float4 bv = *(const float4*)&Bs[k][tx * 4];
            float aa[8] = {a0.x, a0.y, a0.z, a0.w, a1.x, a1.y, a1.z, a1.w};
            float bb[4] = {bv.x, bv.y, bv.z, bv.w};
            #pragma unroll
            for (int i = 0; i < 8; i++)
                #pragma unroll
                for (int j = 0; j < 4; j++)
                    acc[i][j] = fmaf(aa[i], bb[j], acc[i][j]);
        }
        __syncthreads();
    }

    float4 bv = *(const float4*)&bias[n0 + tx * 4];
    float bb[4] = {bv.x, bv.y, bv.z, bv.w};
    #pragma unroll
    for (int i = 0; i < 8; i++) {
        int m = m0 + ty * 8 + i;
        float4 o;
        o.x = acc[i][0] + bb[0];
        o.y = acc[i][1] + bb[1];
        o.z = acc[i][2] + bb[2];
        o.w = acc[i][3] + bb[3];
        *(float4*)&g_h[m * D_OUT + n0 + tx * 4] = o;
    }
}

// ---------------- kernel 2: sq[i] = ||h_i||^2  (one warp per row) -----------
__global__ __launch_bounds__(256) void k_sq() {
    int warp = threadIdx.x >> 5;
    int lane = threadIdx.x & 31;
    int row  = blockIdx.x * 8 + warp;
    const float4* p = (const float4*)&g_h[row * D_OUT];   // 64 float4 per row
    float4 v1 = p[lane];
    float4 v2 = p[lane + 32];
    float s = v1.x * v1.x + v1.y * v1.y + v1.z * v1.z + v1.w * v1.w
            + v2.x * v2.x + v2.y * v2.y + v2.z * v2.z + v2.w * v2.w;
    #pragma unroll
    for (int o = 16; o; o >>= 1) s += __shfl_xor_sync(0xffffffffu, s, o);
    if (lane == 0) g_sq[row] = s;
}

// ---------------- kernel 3: fused Gram tile + hardest pos/neg ---------------
// BM=BN=128, BK=8, 256 threads, 8x8 micro-tile. Grid (32 row-tiles, 8 splits);
// each block sweeps j-tiles {by, by+8, by+16, by+24}. Distance matrix is never
// materialized; per-row max/min combined across blocks via int-atomics (all
// values are non-negative so IEEE bit order == int order).
#define DK 8

__global__ __launch_bounds__(256) void k_dist(const void* __restrict__ targets) {
    __shared__ __align__(16) float As[DK][132];
    __shared__ __align__(16) float Bs[DK][132];

    int tid = threadIdx.x;
    int tx  = tid & 15;          // 16 -> j (8 cols each)
    int ty  = tid >> 4;          // 16 -> i (8 rows each)
    int i0  = blockIdx.x * 128;
    int is64 = g_is64;

    float mp[8], mn[8];
    #pragma unroll
    for (int r = 0; r < 8; r++) { mp[r] = 0.0f; mn[r] = CUDART_INF_F; }

    float sqi[8]; int ci[8];
    #pragma unroll
    for (int r = 0; r < 8; r++) {
        int i = i0 + ty * 8 + r;
        sqi[r] = g_sq[i];
        ci[r]  = get_cls(targets, i, is64);
    }

    int am = tid >> 1;               // 0..127
    int ak = (tid & 1) * 4;          // 0 or 4

    for (int jt = blockIdx.y; jt < 32; jt += 8) {
        int j0 = jt * 128;

        float acc[8][8];
        #pragma unroll
        for (int r = 0; r < 8; r++)
            #pragma unroll
            for (int c = 0; c < 8; c++) acc[r][c] = 0.0f;

        for (int k0 = 0; k0 < D_OUT; k0 += DK) {
            float4 av = *(const float4*)&g_h[(i0 + am) * D_OUT + k0 + ak];
            As[ak + 0][am] = av.x; As[ak + 1][am] = av.y;
            As[ak + 2][am] = av.z; As[ak + 3][am] = av.w;
            float4 bv = *(const float4*)&g_h[(j0 + am) * D_OUT + k0 + ak];
            Bs[ak + 0][am] = bv.x; Bs[ak + 1][am] = bv.y;
            Bs[ak + 2][am] = bv.z; Bs[ak + 3][am] = bv.w;
            __syncthreads();
            #pragma unroll
            for (int k = 0; k < DK; k++) {
                float4 a0 = *(const float4*)&As[k][ty * 8];
                float4 a1 = *(const float4*)&As[k][ty * 8 + 4];
                float4 b0 = *(const float4*)&Bs[k][tx * 8];
                float4 b1 = *(const float4*)&Bs[k][tx * 8 + 4];
                float aa[8] = {a0.x, a0.y, a0.z, a0.w, a1.x, a1.y, a1.z, a1.w};
                float bb[8] = {b0.x, b0.y, b0.z, b0.w, b1.x, b1.y, b1.z, b1.w};
                #pragma unroll
                for (int r = 0; r < 8; r++)
                    #pragma unroll
                    for (int c = 0; c < 8; c++)
                        acc[r][c] = fmaf(aa[r], bb[c], acc[r][c]);
            }
            __syncthreads();
        }

        // epilogue: distance + masked running max/min
        #pragma unroll
        for (int c = 0; c < 8; c++) {
            int j = j0 + tx * 8 + c;
            float sqj = g_sq[j];
            int   cj  = get_cls(targets, j, is64);
            #pragma unroll
            for (int r = 0; r < 8; r++) {
                float d2   = sqi[r] + sqj - 2.0f * acc[r][c];
                float dist = sqrtf(fmaxf(d2, 0.0f));
                if (ci[r] == cj) mp[r] = fmaxf(mp[r], dist);
                else             mn[r] = fminf(mn[r], dist);
            }
        }
    }

    // reduce across the 16 lanes that share the same row set (same ty):
    // those lanes are contiguous within a half-warp, so xor offsets < 16 stay
    // inside the group.
    #pragma unroll
    for (int r = 0; r < 8; r++) {
        float p = mp[r], q = mn[r];
        #pragma unroll
        for (int o = 8; o; o >>= 1) {
            p = fmaxf(p, __shfl_xor_sync(0xffffffffu, p, o));
            q = fminf(q, __shfl_xor_sync(0xffffffffu, q, o));
        }
        if (tx == 0) {
            int i = i0 + ty * 8 + r;
            atomicMax((int*)&g_hp[i], __float_as_int(p));
            atomicMin((int*)&g_hn[i], __float_as_int(q));
        }
    }
}

// ---------------- kernel 4: loss = sum softplus(pos - neg) ------------------
__global__ __launch_bounds__(256) void k_loss(float* __restrict__ out) {
    __shared__ float red[8];
    int tid = threadIdx.x;
    float s = 0.0f;
    for (int i = tid; i < N_SAMPLES; i += 256) {
        float xv = g_hp[i] - g_hn[i];
        float v  = (xv > 20.0f) ? xv : log1pf(expf(xv));
        s += v;
    }
    #pragma unroll
    for (int o = 16; o; o >>= 1) s += __shfl_xor_sync(0xffffffffu, s, o);
    if ((tid & 31) == 0) red[tid >> 5] = s;
    __syncthreads();
    if (tid < 32) {
        float v = (tid < 8) ? red[tid] : 0.0f;
        #pragma unroll
        for (int o = 4; o; o >>= 1) v += __shfl_xor_sync(0xffffffffu, v, o);
        if (tid == 0) out[0] = v;
    }
}

// ---------------- launch ----------------------------------------------------
extern "C" void kernel_launch(void* const* d_in, const int* in_sizes, int n_in,
                              void* d_out, int out_size) {
    const float* x  = (const float*)d_in[0];
    const float* W  = (const float*)d_in[1];
    const float* b  = (const float*)d_in[2];
    const void*  tg = d_in[3];

    k_init<<<1, 1024>>>((const unsigned*)tg);
    k_fc  <<<dim3(D_OUT / FC_BN, N_SAMPLES / FC_BM), 256>>>(x, W, b);
    k_sq  <<<N_SAMPLES / 8, 256>>>();
    k_dist<<<dim3(N_SAMPLES / 128, 8), 256>>>(tg);
    k_loss<<<1, 256>>>((float*)d_out);
}

// round 6
// speedup vs baseline: 1.0046x; 1.0046x over previous
#include <cuda_runtime.h>
#include <math_constants.h>

#define N_SAMPLES 4096
#define D_IN      1024
#define D_OUT     256

// ---------------- persistent device scratch (no allocations allowed) --------
__device__ float    g_h [N_SAMPLES * D_OUT];   // projected features, 4 MB
__device__ float    g_sq[N_SAMPLES];           // ||h_i||^2
__device__ unsigned g_hp[N_SAMPLES];           // enc(max over same-class of sqj-2g)
__device__ unsigned g_hn[N_SAMPLES];           // enc(min over diff-class of sqj-2g)
__device__ int      g_is64;

__device__ __forceinline__ int get_cls(const void* T, int i, int is64) {
    return is64 ? (int)((const long long*)T)[i] : ((const int*)T)[i];
}

// order-preserving float <-> uint encoding (works for negatives / inf)
__device__ __forceinline__ unsigned enc_f(float f) {
    unsigned b = __float_as_uint(f);
    return (b & 0x80000000u) ? ~b : (b | 0x80000000u);
}
__device__ __forceinline__ float dec_f(unsigned u) {
    return __uint_as_float((u & 0x80000000u) ? (u ^ 0x80000000u) : ~u);
}

// packed fp32x2 helpers
__device__ __forceinline__ void ffma2(unsigned long long& d,
                                      unsigned long long a,
                                      unsigned long long b) {
    asm("fma.rn.f32x2 %0, %1, %2, %0;" : "+l"(d) : "l"(a), "l"(b));
}
__device__ __forceinline__ unsigned long long dup2(float v) {
    unsigned long long d;
    asm("mov.b64 %0, {%1, %1};" : "=l"(d) : "r"(__float_as_uint(v)));
    return d;
}
__device__ __forceinline__ void unpack2(unsigned long long v, float& lo, float& hi) {
    unsigned a, b;
    asm("mov.b64 {%0, %1}, %2;" : "=r"(a), "=r"(b) : "l"(v));
    lo = __uint_as_float(a); hi = __uint_as_float(b);
}

// ---------------- kernel 0: dtype detect + per-launch re-init ---------------
__global__ void k_init(const unsigned* __restrict__ twords) {
    __shared__ unsigned red[32];
    int tid = threadIdx.x;
    unsigned acc = 0;
    for (int i = tid; i < 2048; i += 1024) acc |= twords[2 * i + 1];
    #pragma unroll
    for (int o = 16; o; o >>= 1) acc |= __shfl_xor_sync(0xffffffffu, acc, o);
    if ((tid & 31) == 0) red[tid >> 5] = acc;
    __syncthreads();
    if (tid < 32) {
        unsigned v = red[tid];
        #pragma unroll
        for (int o = 16; o; o >>= 1) v |= __shfl_xor_sync(0xffffffffu, v, o);
        if (tid == 0) g_is64 = (v == 0u) ? 1 : 0;
    }
    for (int i = tid; i < N_SAMPLES; i += 1024) {
        g_hp[i] = 0u;           // < enc of any real value (max accumulator)
        g_hn[i] = 0xffffffffu;  // > enc of any real value (min accumulator)
    }
}

// ---------------- kernel 1: h = x @ W + b, f32x2 packed ---------------------
// BM=128, BN=64, BK=8, 256 threads, 8x4 per thread (4 row-pairs x 4 cols).
#define FC_BM 128
#define FC_BN 64
#define FC_BK 8

// duplicated-B offset: col j (0..63) -> word offset of its (b,b) pair
__device__ __forceinline__ int fc_off(int j) {
    int cc = j & 3, txj = j >> 2;
    return (cc >> 1) * 64 + txj * 4 + (cc & 1) * 2;
}

__global__ __launch_bounds__(256) void k_fc(const float* __restrict__ x,
                                            const float* __restrict__ W,
                                            const float* __restrict__ bias) {
    __shared__ __align__(16) float As[FC_BK][132];    // [k][m] transposed, pad
    __shared__ __align__(16) float Bsd[FC_BK][132];   // duplicated pairs, 128 used

    int tid = threadIdx.x;
    int tx  = tid & 15;           // 16 -> n (4 cols each)
    int ty  = tid >> 4;           // 16 -> m (8 rows each = 4 pairs)
    int m0  = blockIdx.y * FC_BM;
    int n0  = blockIdx.x * FC_BN;

    unsigned long long acc2[4][4];
    #pragma unroll
    for (int p = 0; p < 4; p++)
        #pragma unroll
        for (int c = 0; c < 4; c++) acc2[p][c] = 0ull;

    int am = tid >> 1;            // 0..127
    int ak = (tid & 1) * 4;       // 0 or 4
    int bk = tid >> 4;            // (tid<128) 0..7
    int bn = tid & 15;

    for (int k0 = 0; k0 < D_IN; k0 += FC_BK) {
        float4 av = *(const float4*)&x[(m0 + am) * D_IN + k0 + ak];
        As[ak + 0][am] = av.x; As[ak + 1][am] = av.y;
        As[ak + 2][am] = av.z; As[ak + 3][am] = av.w;
        if (tid < 128) {
            float4 bv = *(const float4*)&W[(k0 + bk) * D_OUT + n0 + bn * 4];
            int j = bn * 4;
            *(unsigned long long*)&Bsd[bk][fc_off(j + 0)] = dup2(bv.x);
            *(unsigned long long*)&Bsd[bk][fc_off(j + 1)] = dup2(bv.y);
            *(unsigned long long*)&Bsd[bk][fc_off(j + 2)] = dup2(bv.z);
            *(unsigned long long*)&Bsd[bk][fc_off(j + 3)] = dup2(bv.w);
        }
        __syncthreads();
        #pragma unroll
        for (int k = 0; k < FC_BK; k++) {
            ulonglong2 a01 = *(const ulonglong2*)&As[k][ty * 8];
            ulonglong2 a23 = *(const ulonglong2*)&As[k][ty * 8 + 4];
            ulonglong2 b01 = *(const ulonglong2*)&Bsd[k][tx * 4];
            ulonglong2 b23 = *(const ulonglong2*)&Bsd[k][64 + tx * 4];
            unsigned long long aa[4] = {a01.x, a01.y, a23.x, a23.y};
            unsigned long long bb[4] = {b01.x, b01.y, b23.x, b23.y};
            #pragma unroll
            for (int p = 0; p < 4; p++)
                #pragma unroll
                for (int c = 0; c < 4; c++)
                    ffma2(acc2[p][c], aa[p], bb[c]);
        }
        __syncthreads();
    }

    float4 bv = *(const float4*)&bias[n0 + tx * 4];
    float bb[4] = {bv.x, bv.y, bv.z, bv.w};
    #pragma unroll
    for (int p = 0; p < 4; p++) {
        float lo[4], hi[4];
        #pragma unroll
        for (int c = 0; c < 4; c++) unpack2(acc2[p][c], lo[c], hi[c]);
        int m = m0 + ty * 8 + 2 * p;
        float4 o0 = make_float4(lo[0] + bb[0], lo[1] + bb[1], lo[2] + bb[2], lo[3] + bb[3]);
        float4 o1 = make_float4(hi[0] + bb[0], hi[1] + bb[1], hi[2] + bb[2], hi[3] + bb[3]);
        *(float4*)&g_h[(m + 0) * D_OUT + n0 + tx * 4] = o0;
        *(float4*)&g_h[(m + 1) * D_OUT + n0 + tx * 4] = o1;
    }
}

// ---------------- kernel 2: sq[i] = ||h_i||^2 -------------------------------
__global__ __launch_bounds__(256) void k_sq() {
    int warp = threadIdx.x >> 5;
    int lane = threadIdx.x & 31;
    int row  = blockIdx.x * 8 + warp;
    const float4* p = (const float4*)&g_h[row * D_OUT];
    float4 v1 = p[lane];
    float4 v2 = p[lane + 32];
    float s = v1.x * v1.x + v1.y * v1.y + v1.z * v1.z + v1.w * v1.w
            + v2.x * v2.x + v2.y * v2.y + v2.z * v2.z + v2.w * v2.w;
    #pragma unroll
    for (int o = 16; o; o >>= 1) s += __shfl_xor_sync(0xffffffffu, s, o);
    if (lane == 0) g_sq[row] = s;
}

// ---------------- kernel 3: fused Gram + hardest pos/neg, f32x2 -------------
// BM=BN=128, BK=8, 256 threads, 8x8 per thread as 4 row-pairs x 8 cols.
// B tile stored as duplicated (b,b) pairs in segment layout so every inner
// LDS.128 is lane-contiguous; epilogue tracks val=sqj-2g (monotone), sqrt is
// deferred to k_loss.
#define DK 8

__device__ __forceinline__ int bd_off(int j) {          // j in 0..127
    int cc = j & 7, txj = j >> 3;
    return (cc >> 1) * 64 + txj * 4 + (cc & 1) * 2;     // word offset, even
}

__global__ __launch_bounds__(256) void k_dist(const void* __restrict__ targets) {
    __shared__ __align__(16) float As [DK][132];   // [k][i], pad 4
    __shared__ __align__(16) float Bsd[DK][260];   // duplicated pairs, pad 4

    int tid = threadIdx.x;
    int tx  = tid & 15;          // 16 -> j (8 cols each)
    int ty  = tid >> 4;          // 16 -> i (8 rows = 4 pairs each)
    int i0  = blockIdx.x * 128;
    int is64 = g_is64;

    float mpv[8], mnv[8];
    #pragma unroll
    for (int r = 0; r < 8; r++) { mpv[r] = -CUDART_INF_F; mnv[r] = CUDART_INF_F; }

    int ci[8];
    #pragma unroll
    for (int r = 0; r < 8; r++) ci[r] = get_cls(targets, i0 + ty * 8 + r, is64);

    int am   = tid >> 1;             // 0..127
    int ak   = (tid & 1) * 4;        // 0 or 4
    int offb = bd_off(am);           // dup-pair word offset for row am

    for (int jt = blockIdx.y; jt < 32; jt += 8) {
        int j0 = jt * 128;

        unsigned long long acc2[4][8];
        #pragma unroll
        for (int p = 0; p < 4; p++)
            #pragma unroll
            for (int c = 0; c < 8; c++) acc2[p][c] = 0ull;

        for (int k0 = 0; k0 < D_OUT; k0 += DK) {
            float4 av = *(const float4*)&g_h[(i0 + am) * D_OUT + k0 + ak];
            As[ak + 0][am] = av.x; As[ak + 1][am] = av.y;
            As[ak + 2][am] = av.z; As[ak + 3][am] = av.w;
            float4 bv = *(const float4*)&g_h[(j0 + am) * D_OUT + k0 + ak];
            *(unsigned long long*)&Bsd[ak + 0][offb] = dup2(bv.x);
            *(unsigned long long*)&Bsd[ak + 1][offb] = dup2(bv.y);
            *(unsigned long long*)&Bsd[ak + 2][offb] = dup2(bv.z);
            *(unsigned long long*)&Bsd[ak + 3][offb] = dup2(bv.w);
            __syncthreads();
            #pragma unroll
            for (int k = 0; k < DK; k++) {
                ulonglong2 a01 = *(const ulonglong2*)&As[k][ty * 8];
                ulonglong2 a23 = *(const ulonglong2*)&As[k][ty * 8 + 4];
                unsigned long long aa[4] = {a01.x, a01.y, a23.x, a23.y};
                unsigned long long bb[8];
                #pragma unroll
                for (int s = 0; s < 4; s++) {
                    ulonglong2 b = *(const ulonglong2*)&Bsd[k][s * 64 + tx * 4];
                    bb[2 * s] = b.x; bb[2 * s + 1] = b.y;
                }
                #pragma unroll
                for (int p = 0; p < 4; p++)
                    #pragma unroll
                    for (int c = 0; c < 8; c++)
                        ffma2(acc2[p][c], aa[p], bb[c]);
            }
            __syncthreads();
        }

        // epilogue: val = sqj - 2*g ; masked running max/min (no sqrt here)
        #pragma unroll
        for (int c = 0; c < 8; c++) {
            int j = j0 + tx * 8 + c;
            float sqj = g_sq[j];
            int   cj  = get_cls(targets, j, is64);
            #pragma unroll
            for (int p = 0; p < 4; p++) {
                float glo, ghi;
                unpack2(acc2[p][c], glo, ghi);
                float vlo = fmaf(-2.0f, glo, sqj);
                float vhi = fmaf(-2.0f, ghi, sqj);
                if (ci[2 * p]     == cj) mpv[2 * p]     = fmaxf(mpv[2 * p],     vlo);
                else                     mnv[2 * p]     = fminf(mnv[2 * p],     vlo);
                if (ci[2 * p + 1] == cj) mpv[2 * p + 1] = fmaxf(mpv[2 * p + 1], vhi);
                else                     mnv[2 * p + 1] = fminf(mnv[2 * p + 1], vhi);
            }
        }
    }

    // reduce across the 16 lanes sharing the same rows (contiguous half-warp)
    #pragma unroll
    for (int r = 0; r < 8; r++) {
        float p = mpv[r], q = mnv[r];
        #pragma unroll
        for (int o = 8; o; o >>= 1) {
            p = fmaxf(p, __shfl_xor_sync(0xffffffffu, p, o));
            q = fminf(q, __shfl_xor_sync(0xffffffffu, q, o));
        }
        if (tx == 0) {
            int i = i0 + ty * 8 + r;
            atomicMax(&g_hp[i], enc_f(p));
            atomicMin(&g_hn[i], enc_f(q));
        }
    }
}

// ---------------- kernel 4: loss = sum softplus(hp - hn) --------------------
__global__ __launch_bounds__(256) void k_loss(float* __restrict__ out) {
    __shared__ float red[8];
    int tid = threadIdx.x;
    float s = 0.0f;
    for (int i = tid; i < N_SAMPLES; i += 256) {
        float sqi = g_sq[i];
        float hp = sqrtf(fmaxf(sqi + dec_f(g_hp[i]), 0.0f));
        float hn = sqrtf(fmaxf(sqi + dec_f(g_hn[i]), 0.0f));
        float xv = hp - hn;
        s += (xv > 20.0f) ? xv : log1pf(expf(xv));
    }
    #pragma unroll
    for (int o = 16; o; o >>= 1) s += __shfl_xor_sync(0xffffffffu, s, o);
    if ((tid & 31) == 0) red[tid >> 5] = s;
    __syncthreads();
    if (tid < 32) {
        float v = (tid < 8) ? red[tid] : 0.0f;
        #pragma unroll
        for (int o = 4; o; o >>= 1) v += __shfl_xor_sync(0xffffffffu, v, o);
        if (tid == 0) out[0] = v;
    }
}

// ---------------- launch ----------------------------------------------------
extern "C" void kernel_launch(void* const* d_in, const int* in_sizes, int n_in,
                              void* d_out, int out_size) {
    const float* x  = (const float*)d_in[0];
    const float* W  = (const float*)d_in[1];
    const float* b  = (const float*)d_in[2];
    const void*  tg = d_in[3];

    k_init<<<1, 1024>>>((const unsigned*)tg);
    k_fc  <<<dim3(D_OUT / FC_BN, N_SAMPLES / FC_BM), 256>>>(x, W, b);
    k_sq  <<<N_SAMPLES / 8, 256>>>();
    k_dist<<<dim3(N_SAMPLES / 128, 8), 256>>>(tg);
    k_loss<<<1, 256>>>((float*)d_out);
}

// round 7
// speedup vs baseline: 2.4059x; 2.3949x over previous
#include <cuda_runtime.h>
#include <math_constants.h>

#define N_SAMPLES 4096
#define D_IN      1024
#define D_OUT     256

// ---------------- persistent device scratch (no allocations allowed) --------
__device__ float    g_h [N_SAMPLES * D_OUT];   // projected features, 4 MB
__device__ float    g_sq[N_SAMPLES];           // ||h_i||^2
__device__ unsigned g_hp[N_SAMPLES];           // enc(max over same-class of sqj-2g)
__device__ unsigned g_hn[N_SAMPLES];           // enc(min over diff-class of sqj-2g)
__device__ int      g_is64;

__device__ __forceinline__ int get_cls(const void* T, int i, int is64) {
    return is64 ? (int)((const long long*)T)[i] : ((const int*)T)[i];
}

// order-preserving float <-> uint encoding (handles negatives / inf)
__device__ __forceinline__ unsigned enc_f(float f) {
    unsigned b = __float_as_uint(f);
    return (b & 0x80000000u) ? ~b : (b | 0x80000000u);
}
__device__ __forceinline__ float dec_f(unsigned u) {
    return __uint_as_float((u & 0x80000000u) ? (u ^ 0x80000000u) : ~u);
}

// packed fp32x2 helpers (used by k_fc)
__device__ __forceinline__ void ffma2(unsigned long long& d,
                                      unsigned long long a,
                                      unsigned long long b) {
    asm("fma.rn.f32x2 %0, %1, %2, %0;" : "+l"(d) : "l"(a), "l"(b));
}
__device__ __forceinline__ unsigned long long dup2(float v) {
    unsigned long long d;
    asm("mov.b64 %0, {%1, %1};" : "=l"(d) : "r"(__float_as_uint(v)));
    return d;
}
__device__ __forceinline__ void unpack2(unsigned long long v, float& lo, float& hi) {
    unsigned a, b;
    asm("mov.b64 {%0, %1}, %2;" : "=r"(a), "=r"(b) : "l"(v));
    lo = __uint_as_float(a); hi = __uint_as_float(b);
}

// tf32 warp mma: D = A(16x8) * B(8x8) + D, fp32 accumulate, raw fp32 bits as tf32
__device__ __forceinline__ void mma_tf32(float* d, const unsigned* a, const unsigned* b) {
    asm volatile(
        "mma.sync.aligned.m16n8k8.row.col.f32.tf32.tf32.f32 "
        "{%0,%1,%2,%3}, {%4,%5,%6,%7}, {%8,%9}, {%0,%1,%2,%3};"
        : "+f"(d[0]), "+f"(d[1]), "+f"(d[2]), "+f"(d[3])
        : "r"(a[0]), "r"(a[1]), "r"(a[2]), "r"(a[3]), "r"(b[0]), "r"(b[1]));
}

// ---------------- kernel 0: dtype detect + per-launch re-init ---------------
__global__ void k_init(const unsigned* __restrict__ twords) {
    __shared__ unsigned red[32];
    int tid = threadIdx.x;
    unsigned acc = 0;
    for (int i = tid; i < 2048; i += 1024) acc |= twords[2 * i + 1];
    #pragma unroll
    for (int o = 16; o; o >>= 1) acc |= __shfl_xor_sync(0xffffffffu, acc, o);
    if ((tid & 31) == 0) red[tid >> 5] = acc;
    __syncthreads();
    if (tid < 32) {
        unsigned v = red[tid];
        #pragma unroll
        for (int o = 16; o; o >>= 1) v |= __shfl_xor_sync(0xffffffffu, v, o);
        if (tid == 0) g_is64 = (v == 0u) ? 1 : 0;
    }
    for (int i = tid; i < N_SAMPLES; i += 1024) {
        g_hp[i] = 0u;
        g_hn[i] = 0xffffffffu;
    }
}

// ---------------- kernel 1: h = x @ W + b, f32x2 packed (fp32-exact) --------
#define FC_BM 128
#define FC_BN 64
#define FC_BK 8

__device__ __forceinline__ int fc_off(int j) {
    int cc = j & 3, txj = j >> 2;
    return (cc >> 1) * 64 + txj * 4 + (cc & 1) * 2;
}

__global__ __launch_bounds__(256) void k_fc(const float* __restrict__ x,
                                            const float* __restrict__ W,
                                            const float* __restrict__ bias) {
    __shared__ __align__(16) float As[FC_BK][132];
    __shared__ __align__(16) float Bsd[FC_BK][132];

    int tid = threadIdx.x;
    int tx  = tid & 15;
    int ty  = tid >> 4;
    int m0  = blockIdx.y * FC_BM;
    int n0  = blockIdx.x * FC_BN;

    unsigned long long acc2[4][4];
    #pragma unroll
    for (int p = 0; p < 4; p++)
        #pragma unroll
        for (int c = 0; c < 4; c++) acc2[p][c] = 0ull;

    int am = tid >> 1;
    int ak = (tid & 1) * 4;
    int bk = tid >> 4;
    int bn = tid & 15;

    for (int k0 = 0; k0 < D_IN; k0 += FC_BK) {
        float4 av = *(const float4*)&x[(m0 + am) * D_IN + k0 + ak];
        As[ak + 0][am] = av.x; As[ak + 1][am] = av.y;
        As[ak + 2][am] = av.z; As[ak + 3][am] = av.w;
        if (tid < 128) {
            float4 bv = *(const float4*)&W[(k0 + bk) * D_OUT + n0 + bn * 4];
            int j = bn * 4;
            *(unsigned long long*)&Bsd[bk][fc_off(j + 0)] = dup2(bv.x);
            *(unsigned long long*)&Bsd[bk][fc_off(j + 1)] = dup2(bv.y);
            *(unsigned long long*)&Bsd[bk][fc_off(j + 2)] = dup2(bv.z);
            *(unsigned long long*)&Bsd[bk][fc_off(j + 3)] = dup2(bv.w);
        }
        __syncthreads();
        #pragma unroll
        for (int k = 0; k < FC_BK; k++) {
            ulonglong2 a01 = *(const ulonglong2*)&As[k][ty * 8];
            ulonglong2 a23 = *(const ulonglong2*)&As[k][ty * 8 + 4];
            ulonglong2 b01 = *(const ulonglong2*)&Bsd[k][tx * 4];
            ulonglong2 b23 = *(const ulonglong2*)&Bsd[k][64 + tx * 4];
            unsigned long long aa[4] = {a01.x, a01.y, a23.x, a23.y};
            unsigned long long bb[4] = {b01.x, b01.y, b23.x, b23.y};
            #pragma unroll
            for (int p = 0; p < 4; p++)
                #pragma unroll
                for (int c = 0; c < 4; c++)
                    ffma2(acc2[p][c], aa[p], bb[c]);
        }
        __syncthreads();
    }

    float4 bv = *(const float4*)&bias[n0 + tx * 4];
    float bb[4] = {bv.x, bv.y, bv.z, bv.w};
    #pragma unroll
    for (int p = 0; p < 4; p++) {
        float lo[4], hi[4];
        #pragma unroll
        for (int c = 0; c < 4; c++) unpack2(acc2[p][c], lo[c], hi[c]);
        int m = m0 + ty * 8 + 2 * p;
        float4 o0 = make_float4(lo[0] + bb[0], lo[1] + bb[1], lo[2] + bb[2], lo[3] + bb[3]);
        float4 o1 = make_float4(hi[0] + bb[0], hi[1] + bb[1], hi[2] + bb[2], hi[3] + bb[3]);
        *(float4*)&g_h[(m + 0) * D_OUT + n0 + tx * 4] = o0;
        *(float4*)&g_h[(m + 1) * D_OUT + n0 + tx * 4] = o1;
    }
}

// ---------------- kernel 2: sq[i] = ||h_i||^2 -------------------------------
__global__ __launch_bounds__(256) void k_sq() {
    int warp = threadIdx.x >> 5;
    int lane = threadIdx.x & 31;
    int row  = blockIdx.x * 8 + warp;
    const float4* p = (const float4*)&g_h[row * D_OUT];
    float4 v1 = p[lane];
    float4 v2 = p[lane + 32];
    float s = v1.x * v1.x + v1.y * v1.y + v1.z * v1.z + v1.w * v1.w
            + v2.x * v2.x + v2.y * v2.y + v2.z * v2.z + v2.w * v2.w;
    #pragma unroll
    for (int o = 16; o; o >>= 1) s += __shfl_xor_sync(0xffffffffu, s, o);
    if (lane == 0) g_sq[row] = s;
}

// ---------------- kernel 3: Gram via tf32 tensor-core mma + hardest pos/neg -
// Block = 128x128 tile of H·Hᵀ. 8 warps as 4(row)x2(col); warp = 32x64 =
// 2x8 m16n8k8 tiles. K staged in smem chunks of 32, row stride 36 words so
// every fragment-load pattern (addr = const + 36g + t) is bank-conflict-free.
// Epilogue tracks val = sq_j - 2*g (monotone in dist); sqrt deferred to k_loss.
#define D_BK 32
#define D_LDJ 36

__global__ __launch_bounds__(256, 2) void k_dist(const void* __restrict__ targets) {
    __shared__ __align__(16) float As[128][D_LDJ];
    __shared__ __align__(16) float Bs[128][D_LDJ];
    __shared__ float s_sq[128];
    __shared__ int   s_cl[128];

    int tid  = threadIdx.x;
    int lane = tid & 31;
    int wid  = tid >> 5;
    int wm   = wid & 3;          // 4 row-groups of 32
    int wn   = wid >> 2;         // 2 col-groups of 64
    int g    = lane >> 2;        // groupID 0..7
    int t    = lane & 3;         // threadID_in_group
    int i0   = blockIdx.x * 128;
    int is64 = g_is64;

    // classes for this thread's 4 accumulator rows
    int ci4[4];
    #pragma unroll
    for (int r = 0; r < 4; r++)
        ci4[r] = get_cls(targets, i0 + wm * 32 + (r >> 1) * 16 + (r & 1) * 8 + g, is64);

    float mp[4], mn[4];
    #pragma unroll
    for (int r = 0; r < 4; r++) { mp[r] = -CUDART_INF_F; mn[r] = CUDART_INF_F; }

    for (int jt = blockIdx.y; jt < 32; jt += 8) {
        int j0 = jt * 128;

        float acc[2][8][4];
        #pragma unroll
        for (int tm = 0; tm < 2; tm++)
            #pragma unroll
            for (int tn = 0; tn < 8; tn++)
                #pragma unroll
                for (int c = 0; c < 4; c++) acc[tm][tn][c] = 0.0f;

        for (int k0 = 0; k0 < D_OUT; k0 += D_BK) {
            __syncthreads();
            // fill A/B tiles: 1024 float4 each, 4 per thread
            #pragma unroll
            for (int v = 0; v < 4; v++) {
                int idx = tid + v * 256;
                int row = idx >> 3, c4 = (idx & 7) * 4;
                *(float4*)&As[row][c4] = *(const float4*)&g_h[(i0 + row) * D_OUT + k0 + c4];
                *(float4*)&Bs[row][c4] = *(const float4*)&g_h[(j0 + row) * D_OUT + k0 + c4];
            }
            if (k0 == 0 && tid < 128) {
                s_sq[tid] = g_sq[j0 + tid];
                s_cl[tid] = get_cls(targets, j0 + tid, is64);
            }
            __syncthreads();

            #pragma unroll
            for (int ks = 0; ks < D_BK / 8; ks++) {
                int kk = ks * 8;
                unsigned a[2][4], b[8][2];
                #pragma unroll
                for (int tm = 0; tm < 2; tm++) {
                    int r = wm * 32 + tm * 16 + g;
                    a[tm][0] = __float_as_uint(As[r    ][kk + t    ]);
                    a[tm][1] = __float_as_uint(As[r + 8][kk + t    ]);
                    a[tm][2] = __float_as_uint(As[r    ][kk + t + 4]);
                    a[tm][3] = __float_as_uint(As[r + 8][kk + t + 4]);
                }
                #pragma unroll
                for (int tn = 0; tn < 8; tn++) {
                    int c = wn * 64 + tn * 8 + g;
                    b[tn][0] = __float_as_uint(Bs[c][kk + t    ]);
                    b[tn][1] = __float_as_uint(Bs[c][kk + t + 4]);
                }
                #pragma unroll
                for (int tm = 0; tm < 2; tm++)
                    #pragma unroll
                    for (int tn = 0; tn < 8; tn++)
                        mma_tf32(acc[tm][tn], a[tm], b[tn]);
            }
        }

        // epilogue: val = sq_j - 2*g_ij ; masked running max/min
        // C fragment: c0=(g, 2t) c1=(g, 2t+1) c2=(g+8, 2t) c3=(g+8, 2t+1)
        #pragma unroll
        for (int tn = 0; tn < 8; tn++) {
            int c = wn * 64 + tn * 8 + 2 * t;
            float sq1 = s_sq[c], sq2 = s_sq[c + 1];
            int   cl1 = s_cl[c], cl2 = s_cl[c + 1];
            #pragma unroll
            for (int tm = 0; tm < 2; tm++) {
                float v00 = fmaf(-2.0f, acc[tm][tn][0], sq1);
                float v01 = fmaf(-2.0f, acc[tm][tn][1], sq2);
                float v10 = fmaf(-2.0f, acc[tm][tn][2], sq1);
                float v11 = fmaf(-2.0f, acc[tm][tn][3], sq2);
                int r0 = tm * 2, r1 = tm * 2 + 1;
                if (ci4[r0] == cl1) mp[r0] = fmaxf(mp[r0], v00); else mn[r0] = fminf(mn[r0], v00);
                if (ci4[r0] == cl2) mp[r0] = fmaxf(mp[r0], v01); else mn[r0] = fminf(mn[r0], v01);
                if (ci4[r1] == cl1) mp[r1] = fmaxf(mp[r1], v10); else mn[r1] = fminf(mn[r1], v10);
                if (ci4[r1] == cl2) mp[r1] = fmaxf(mp[r1], v11); else mn[r1] = fminf(mn[r1], v11);
            }
        }
    }

    // reduce over the 4 lanes of each quad (same g => same rows, xor 1/2 stay in quad)
    #pragma unroll
    for (int r = 0; r < 4; r++) {
        float p = mp[r], q = mn[r];
        #pragma unroll
        for (int o = 2; o; o >>= 1) {
            p = fmaxf(p, __shfl_xor_sync(0xffffffffu, p, o));
            q = fminf(q, __shfl_xor_sync(0xffffffffu, q, o));
        }
        if (t == 0) {
            int i = i0 + wm * 32 + (r >> 1) * 16 + (r & 1) * 8 + g;
            atomicMax(&g_hp[i], enc_f(p));
            atomicMin(&g_hn[i], enc_f(q));
        }
    }
}

// ---------------- kernel 4: loss = sum softplus(hp - hn) --------------------
__global__ __launch_bounds__(256) void k_loss(float* __restrict__ out) {
    __shared__ float red[8];
    int tid = threadIdx.x;
    float s = 0.0f;
    for (int i = tid; i < N_SAMPLES; i += 256) {
        float sqi = g_sq[i];
        float hp = sqrtf(fmaxf(sqi + dec_f(g_hp[i]), 0.0f));
        float hn = sqrtf(fmaxf(sqi + dec_f(g_hn[i]), 0.0f));
        float xv = hp - hn;
        s += (xv > 20.0f) ? xv : log1pf(expf(xv));
    }
    #pragma unroll
    for (int o = 16; o; o >>= 1) s += __shfl_xor_sync(0xffffffffu, s, o);
    if ((tid & 31) == 0) red[tid >> 5] = s;
    __syncthreads();
    if (tid < 32) {
        float v = (tid < 8) ? red[tid] : 0.0f;
        #pragma unroll
        for (int o = 4; o; o >>= 1) v += __shfl_xor_sync(0xffffffffu, v, o);
        if (tid == 0) out[0] = v;
    }
}

// ---------------- launch ----------------------------------------------------
extern "C" void kernel_launch(void* const* d_in, const int* in_sizes, int n_in,
                              void* d_out, int out_size) {
    const float* x  = (const float*)d_in[0];
    const float* W  = (const float*)d_in[1];
    const float* b  = (const float*)d_in[2];
    const void*  tg = d_in[3];

    k_init<<<1, 1024>>>((const unsigned*)tg);
    k_fc  <<<dim3(D_OUT / FC_BN, N_SAMPLES / FC_BM), 256>>>(x, W, b);
    k_sq  <<<N_SAMPLES / 8, 256>>>();
    k_dist<<<dim3(N_SAMPLES / 128, 8), 256>>>(tg);
    k_loss<<<1, 256>>>((float*)d_out);
}

// round 9
// speedup vs baseline: 3.3103x; 1.3759x over previous
#include <cuda_runtime.h>
#include <math_constants.h>

#define N_SAMPLES 4096
#define D_IN      1024
#define D_OUT     256

// ---------------- persistent device scratch (no allocations allowed) --------
__device__ float    g_h [N_SAMPLES * D_OUT];   // projected features, 4 MB
__device__ float    g_sq[N_SAMPLES];           // ||h_i||^2 (atomic-accumulated)
__device__ unsigned g_hp[N_SAMPLES];           // enc(max over same-class of sqj-2g)
__device__ unsigned g_hn[N_SAMPLES];           // enc(min over diff-class of sqj-2g)
__device__ int      g_is64;

__device__ __forceinline__ int get_cls(const void* T, int i, int is64) {
    return is64 ? (int)((const long long*)T)[i] : ((const int*)T)[i];
}

// order-preserving float <-> uint encoding (handles negatives / inf)
__device__ __forceinline__ unsigned enc_f(float f) {
    unsigned b = __float_as_uint(f);
    return (b & 0x80000000u) ? ~b : (b | 0x80000000u);
}
__device__ __forceinline__ float dec_f(unsigned u) {
    return __uint_as_float((u & 0x80000000u) ? (u ^ 0x80000000u) : ~u);
}

// tf32 warp mma: D = A(16x8) * B(8x8) + D, fp32 accumulate
__device__ __forceinline__ void mma_tf32(float* d, const unsigned* a, const unsigned* b) {
    asm volatile(
        "mma.sync.aligned.m16n8k8.row.col.f32.tf32.tf32.f32 "
        "{%0,%1,%2,%3}, {%4,%5,%6,%7}, {%8,%9}, {%0,%1,%2,%3};"
        : "+f"(d[0]), "+f"(d[1]), "+f"(d[2]), "+f"(d[3])
        : "r"(a[0]), "r"(a[1]), "r"(a[2]), "r"(a[3]), "r"(b[0]), "r"(b[1]));
}

// round-to-nearest tf32 (top bits), exact residual in fp32
__device__ __forceinline__ unsigned tf32_hi(float x) {
    unsigned r;
    asm("cvt.rna.tf32.f32 %0, %1;" : "=r"(r) : "f"(x));
    return r;
}

// ---------------- kernel 0: dtype detect + per-launch re-init ---------------
__global__ void k_init(const unsigned* __restrict__ twords) {
    __shared__ unsigned red[32];
    int tid = threadIdx.x;
    unsigned acc = 0;
    for (int i = tid; i < 2048; i += 1024) acc |= twords[2 * i + 1];
    #pragma unroll
    for (int o = 16; o; o >>= 1) acc |= __shfl_xor_sync(0xffffffffu, acc, o);
    if ((tid & 31) == 0) red[tid >> 5] = acc;
    __syncthreads();
    if (tid < 32) {
        unsigned v = red[tid];
        #pragma unroll
        for (int o = 16; o; o >>= 1) v |= __shfl_xor_sync(0xffffffffu, v, o);
        if (tid == 0) g_is64 = (v == 0u) ? 1 : 0;
    }
    for (int i = tid; i < N_SAMPLES; i += 1024) {
        g_hp[i] = 0u;
        g_hn[i] = 0xffffffffu;
        g_sq[i] = 0.0f;
    }
}

// ---------------- kernel 1: h = x @ W + b via 3xTF32 mma, fused ||h||^2 -----
// BM=128, BN=64, BK=32. 8 warps as 4(row)x2(col); warp = 32x32 = 2x4 mma tiles.
// Xs stride 36 (bank pattern g*4+t), Ws natural [k][n] stride 72 (t*8+g).
// 3xTF32: acc += ah*bh + ah*bl + al*bh  -> ~fp32-accurate h.
#define FC_BK 32
#define XS_S  36
#define WS_S  72

__global__ __launch_bounds__(256, 2) void k_fc(const float* __restrict__ x,
                                               const float* __restrict__ W,
                                               const float* __restrict__ bias) {
    __shared__ __align__(16) float Xs[128][XS_S];
    __shared__ __align__(16) float Ws[FC_BK][WS_S];

    int tid  = threadIdx.x;
    int lane = tid & 31;
    int wid  = tid >> 5;
    int wm   = wid & 3;           // 4 row-groups of 32
    int wn   = wid >> 2;          // 2 col-groups of 32
    int g    = lane >> 2;
    int t    = lane & 3;
    int m0   = blockIdx.y * 128;
    int n0   = blockIdx.x * 64;

    float acc[2][4][4];
    #pragma unroll
    for (int tm = 0; tm < 2; tm++)
        #pragma unroll
        for (int tn = 0; tn < 4; tn++)
            #pragma unroll
            for (int c = 0; c < 4; c++) acc[tm][tn][c] = 0.0f;

    for (int k0 = 0; k0 < D_IN; k0 += FC_BK) {
        __syncthreads();
        #pragma unroll
        for (int v = 0; v < 4; v++) {           // X tile: 128x32 = 1024 float4
            int idx = tid + v * 256;
            int row = idx >> 3, c4 = (idx & 7) * 4;
            *(float4*)&Xs[row][c4] = *(const float4*)&x[(m0 + row) * D_IN + k0 + c4];
        }
        #pragma unroll
        for (int v = 0; v < 2; v++) {           // W tile: 32x64 = 512 float4
            int idx = tid + v * 256;
            int kr = idx >> 4, c4 = (idx & 15) * 4;
            *(float4*)&Ws[kr][c4] = *(const float4*)&W[(k0 + kr) * D_OUT + n0 + c4];
        }
        __syncthreads();

        #pragma unroll
        for (int ks = 0; ks < FC_BK / 8; ks++) {
            int kk = ks * 8;
            unsigned ah[2][4], al[2][4], bh[4][2], bl[4][2];
            #pragma unroll
            for (int tm = 0; tm < 2; tm++) {
                int r = wm * 32 + tm * 16 + g;
                float f0 = Xs[r    ][kk + t    ];
                float f1 = Xs[r + 8][kk + t    ];
                float f2 = Xs[r    ][kk + t + 4];
                float f3 = Xs[r + 8][kk + t + 4];
                ah[tm][0] = tf32_hi(f0); al[tm][0] = __float_as_uint(f0 - __uint_as_float(ah[tm][0]));
                ah[tm][1] = tf32_hi(f1); al[tm][1] = __float_as_uint(f1 - __uint_as_float(ah[tm][1]));
                ah[tm][2] = tf32_hi(f2); al[tm][2] = __float_as_uint(f2 - __uint_as_float(ah[tm][2]));
                ah[tm][3] = tf32_hi(f3); al[tm][3] = __float_as_uint(f3 - __uint_as_float(ah[tm][3]));
            }
            #pragma unroll
            for (int tn = 0; tn < 4; tn++) {
                int c = wn * 32 + tn * 8 + g;
                float f0 = Ws[kk + t    ][c];
                float f1 = Ws[kk + t + 4][c];
                bh[tn][0] = tf32_hi(f0); bl[tn][0] = __float_as_uint(f0 - __uint_as_float(bh[tn][0]));
                bh[tn][1] = tf32_hi(f1); bl[tn][1] = __float_as_uint(f1 - __uint_as_float(bh[tn][1]));
            }
            #pragma unroll
            for (int tm = 0; tm < 2; tm++)
                #pragma unroll
                for (int tn = 0; tn < 4; tn++) {
                    mma_tf32(acc[tm][tn], ah[tm], bh[tn]);
                    mma_tf32(acc[tm][tn], ah[tm], bl[tn]);
                    mma_tf32(acc[tm][tn], al[tm], bh[tn]);
                }
        }
    }

    // epilogue: + bias, store h, fused partial ||h_row||^2 via quad-reduce+atomic
    float ssum[4] = {0.0f, 0.0f, 0.0f, 0.0f};   // rows: [tm*2 + (0:r, 1:r+8)]
    #pragma unroll
    for (int tn = 0; tn < 4; tn++) {
        int c = n0 + wn * 32 + tn * 8 + 2 * t;
        float b0 = bias[c], b1 = bias[c + 1];
        #pragma unroll
        for (int tm = 0; tm < 2; tm++) {
            int r0 = m0 + wm * 32 + tm * 16 + g;
            float o00 = acc[tm][tn][0] + b0, o01 = acc[tm][tn][1] + b1;
            float o10 = acc[tm][tn][2] + b0, o11 = acc[tm][tn][3] + b1;
            *(float2*)&g_h[r0 * D_OUT + c]       = make_float2(o00, o01);
            *(float2*)&g_h[(r0 + 8) * D_OUT + c] = make_float2(o10, o11);
            ssum[tm * 2 + 0] += o00 * o00 + o01 * o01;
            ssum[tm * 2 + 1] += o10 * o10 + o11 * o11;
        }
    }
    #pragma unroll
    for (int rr = 0; rr < 4; rr++) {
        float s = ssum[rr];
        s += __shfl_xor_sync(0xffffffffu, s, 1);
        s += __shfl_xor_sync(0xffffffffu, s, 2);
        if (t == 0) {
            int r = m0 + wm * 32 + (rr >> 1) * 16 + (rr & 1) * 8 + g;
            atomicAdd(&g_sq[r], s);
        }
    }
}

// ---------------- kernel 3: Gram via tf32 mma + hardest pos/neg -------------
#define D_BK 32
#define D_LDJ 36

__global__ __launch_bounds__(256, 2) void k_dist(const void* __restrict__ targets) {
    __shared__ __align__(16) float As[128][D_LDJ];
    __shared__ __align__(16) float Bs[128][D_LDJ];
    __shared__ float s_sq[128];
    __shared__ int   s_cl[128];

    int tid  = threadIdx.x;
    int lane = tid & 31;
    int wid  = tid >> 5;
    int wm   = wid & 3;          // 4 row-groups of 32
    int wn   = wid >> 2;         // 2 col-groups of 64
    int g    = lane >> 2;
    int t    = lane & 3;
    int i0   = blockIdx.x * 128;
    int is64 = g_is64;

    int ci4[4];
    #pragma unroll
    for (int r = 0; r < 4; r++)
        ci4[r] = get_cls(targets, i0 + wm * 32 + (r >> 1) * 16 + (r & 1) * 8 + g, is64);

    float mp[4], mn[4];
    #pragma unroll
    for (int r = 0; r < 4; r++) { mp[r] = -CUDART_INF_F; mn[r] = CUDART_INF_F; }

    for (int jt = blockIdx.y; jt < 32; jt += 8) {
        int j0 = jt * 128;

        float acc[2][8][4];
        #pragma unroll
        for (int tm = 0; tm < 2; tm++)
            #pragma unroll
            for (int tn = 0; tn < 8; tn++)
                #pragma unroll
                for (int c = 0; c < 4; c++) acc[tm][tn][c] = 0.0f;

        for (int k0 = 0; k0 < D_OUT; k0 += D_BK) {
            __syncthreads();
            #pragma unroll
            for (int v = 0; v < 4; v++) {
                int idx = tid + v * 256;
                int row = idx >> 3, c4 = (idx & 7) * 4;
                *(float4*)&As[row][c4] = *(const float4*)&g_h[(i0 + row) * D_OUT + k0 + c4];
                *(float4*)&Bs[row][c4] = *(const float4*)&g_h[(j0 + row) * D_OUT + k0 + c4];
            }
            if (k0 == 0 && tid < 128) {
                s_sq[tid] = g_sq[j0 + tid];
                s_cl[tid] = get_cls(targets, j0 + tid, is64);
            }
            __syncthreads();

            #pragma unroll
            for (int ks = 0; ks < D_BK / 8; ks++) {
                int kk = ks * 8;
                unsigned a[2][4], b[8][2];
                #pragma unroll
                for (int tm = 0; tm < 2; tm++) {
                    int r = wm * 32 + tm * 16 + g;
                    a[tm][0] = __float_as_uint(As[r    ][kk + t    ]);
                    a[tm][1] = __float_as_uint(As[r + 8][kk + t    ]);
                    a[tm][2] = __float_as_uint(As[r    ][kk + t + 4]);
                    a[tm][3] = __float_as_uint(As[r + 8][kk + t + 4]);
                }
                #pragma unroll
                for (int tn = 0; tn < 8; tn++) {
                    int c = wn * 64 + tn * 8 + g;
                    b[tn][0] = __float_as_uint(Bs[c][kk + t    ]);
                    b[tn][1] = __float_as_uint(Bs[c][kk + t + 4]);
                }
                #pragma unroll
                for (int tm = 0; tm < 2; tm++)
                    #pragma unroll
                    for (int tn = 0; tn < 8; tn++)
                        mma_tf32(acc[tm][tn], a[tm], b[tn]);
            }
        }

        #pragma unroll
        for (int tn = 0; tn < 8; tn++) {
            int c = wn * 64 + tn * 8 + 2 * t;
            float sq1 = s_sq[c], sq2 = s_sq[c + 1];
            int   cl1 = s_cl[c], cl2 = s_cl[c + 1];
            #pragma unroll
            for (int tm = 0; tm < 2; tm++) {
                float v00 = fmaf(-2.0f, acc[tm][tn][0], sq1);
                float v01 = fmaf(-2.0f, acc[tm][tn][1], sq2);
                float v10 = fmaf(-2.0f, acc[tm][tn][2], sq1);
                float v11 = fmaf(-2.0f, acc[tm][tn][3], sq2);
                int r0 = tm * 2, r1 = tm * 2 + 1;
                if (ci4[r0] == cl1) mp[r0] = fmaxf(mp[r0], v00); else mn[r0] = fminf(mn[r0], v00);
                if (ci4[r0] == cl2) mp[r0] = fmaxf(mp[r0], v01); else mn[r0] = fminf(mn[r0], v01);
                if (ci4[r1] == cl1) mp[r1] = fmaxf(mp[r1], v10); else mn[r1] = fminf(mn[r1], v10);
                if (ci4[r1] == cl2) mp[r1] = fmaxf(mp[r1], v11); else mn[r1] = fminf(mn[r1], v11);
            }
        }
    }

    #pragma unroll
    for (int r = 0; r < 4; r++) {
        float p = mp[r], q = mn[r];
        #pragma unroll
        for (int o = 2; o; o >>= 1) {
            p = fmaxf(p, __shfl_xor_sync(0xffffffffu, p, o));
            q = fminf(q, __shfl_xor_sync(0xffffffffu, q, o));
        }
        if (t == 0) {
            int i = i0 + wm * 32 + (r >> 1) * 16 + (r & 1) * 8 + g;
            atomicMax(&g_hp[i], enc_f(p));
            atomicMin(&g_hn[i], enc_f(q));
        }
    }
}

// ---------------- kernel 4: loss = sum softplus(hp - hn) --------------------
__global__ __launch_bounds__(256) void k_loss(float* __restrict__ out) {
    __shared__ float red[8];
    int tid = threadIdx.x;
    float s = 0.0f;
    for (int i = tid; i < N_SAMPLES; i += 256) {
        float sqi = g_sq[i];
        float hp = sqrtf(fmaxf(sqi + dec_f(g_hp[i]), 0.0f));
        float hn = sqrtf(fmaxf(sqi + dec_f(g_hn[i]), 0.0f));
        float xv = hp - hn;
        s += (xv > 20.0f) ? xv : log1pf(expf(xv));
    }
    #pragma unroll
    for (int o = 16; o; o >>= 1) s += __shfl_xor_sync(0xffffffffu, s, o);
    if ((tid & 31) == 0) red[tid >> 5] = s;
    __syncthreads();
    if (tid < 32) {
        float v = (tid < 8) ? red[tid] : 0.0f;
        #pragma unroll
        for (int o = 4; o; o >>= 1) v += __shfl_xor_sync(0xffffffffu, v, o);
        if (tid == 0) out[0] = v;
    }
}

// ---------------- launch ----------------------------------------------------
extern "C" void kernel_launch(void* const* d_in, const int* in_sizes, int n_in,
                              void* d_out, int out_size) {
    const float* x  = (const float*)d_in[0];
    const float* W  = (const float*)d_in[1];
    const float* b  = (const float*)d_in[2];
    const void*  tg = d_in[3];

    k_init<<<1, 1024>>>((const unsigned*)tg);
    k_fc  <<<dim3(D_OUT / 64, N_SAMPLES / 128), 256>>>(x, W, b);
    k_dist<<<dim3(N_SAMPLES / 128, 8), 256>>>(tg);
    k_loss<<<1, 256>>>((float*)d_out);
}

// round 10
// speedup vs baseline: 3.9658x; 1.1980x over previous
#include <cuda_runtime.h>
#include <math_constants.h>

#define N_SAMPLES 4096
#define D_IN      1024
#define D_OUT     256

// ---------------- persistent device scratch (no allocations allowed) --------
__device__ float    g_h [N_SAMPLES * D_OUT];   // projected features, 4 MB
__device__ float    g_sq[N_SAMPLES];           // ||h_i||^2 (atomic-accumulated)
__device__ unsigned g_hp[N_SAMPLES];           // enc(max over same-class of sqj-2g)
__device__ unsigned g_hn[N_SAMPLES];           // enc(min over diff-class of sqj-2g)
__device__ int      g_is64;

__device__ __forceinline__ int get_cls(const void* T, int i, int is64) {
    return is64 ? (int)((const long long*)T)[i] : ((const int*)T)[i];
}

// order-preserving float <-> uint encoding (handles negatives / inf)
__device__ __forceinline__ unsigned enc_f(float f) {
    unsigned b = __float_as_uint(f);
    return (b & 0x80000000u) ? ~b : (b | 0x80000000u);
}
__device__ __forceinline__ float dec_f(unsigned u) {
    return __uint_as_float((u & 0x80000000u) ? (u ^ 0x80000000u) : ~u);
}

// tf32 warp mma: D = A(16x8) * B(8x8) + D, fp32 accumulate
__device__ __forceinline__ void mma_tf32(float* d, const unsigned* a, const unsigned* b) {
    asm volatile(
        "mma.sync.aligned.m16n8k8.row.col.f32.tf32.tf32.f32 "
        "{%0,%1,%2,%3}, {%4,%5,%6,%7}, {%8,%9}, {%0,%1,%2,%3};"
        : "+f"(d[0]), "+f"(d[1]), "+f"(d[2]), "+f"(d[3])
        : "r"(a[0]), "r"(a[1]), "r"(a[2]), "r"(a[3]), "r"(b[0]), "r"(b[1]));
}

__device__ __forceinline__ unsigned tf32_hi(float x) {
    unsigned r;
    asm("cvt.rna.tf32.f32 %0, %1;" : "=r"(r) : "f"(x));
    return r;
}

// cp.async helpers (16B, L2-only .cg path)
__device__ __forceinline__ void cp16(const void* smem_dst, const void* gmem_src) {
    unsigned s = (unsigned)__cvta_generic_to_shared(smem_dst);
    asm volatile("cp.async.cg.shared.global [%0], [%1], 16;" :: "r"(s), "l"(gmem_src));
}
#define CP_COMMIT() asm volatile("cp.async.commit_group;" ::: "memory")
#define CP_WAIT1()  asm volatile("cp.async.wait_group 1;" ::: "memory")
#define CP_WAIT0()  asm volatile("cp.async.wait_group 0;" ::: "memory")

// ---------------- kernel 0: dtype detect + per-launch re-init ---------------
__global__ void k_init(const unsigned* __restrict__ twords, float* __restrict__ out) {
    __shared__ unsigned red[32];
    int tid = threadIdx.x;
    unsigned acc = 0;
    for (int i = tid; i < 2048; i += 1024) acc |= twords[2 * i + 1];
    #pragma unroll
    for (int o = 16; o; o >>= 1) acc |= __shfl_xor_sync(0xffffffffu, acc, o);
    if ((tid & 31) == 0) red[tid >> 5] = acc;
    __syncthreads();
    if (tid < 32) {
        unsigned v = red[tid];
        #pragma unroll
        for (int o = 16; o; o >>= 1) v |= __shfl_xor_sync(0xffffffffu, v, o);
        if (tid == 0) g_is64 = (v == 0u) ? 1 : 0;
    }
    if (tid == 0) out[0] = 0.0f;
    for (int i = tid; i < N_SAMPLES; i += 1024) {
        g_hp[i] = 0u;
        g_hn[i] = 0xffffffffu;
        g_sq[i] = 0.0f;
    }
}

// ---------------- kernel 1: h = x @ W + b via 3xTF32 mma, fused ||h||^2 -----
// BM=128, BN=64, BK=32, double-buffered cp.async pipeline.
// Xs stride 36 words (bank-clean), Ws natural [k][n] stride 72 words.
#define FC_BK   32
#define FC_XW   (128 * 36)          // one X buffer, words
#define FC_WW   (FC_BK * 72)        // one W buffer, words
#define FC_SMEM ((2 * FC_XW + 2 * FC_WW) * 4)

#define XS(b, r, c) fsm[(b) * FC_XW + (r) * 36 + (c)]
#define WS(b, k, c) fsm[2 * FC_XW + (b) * FC_WW + (k) * 72 + (c)]

__global__ __launch_bounds__(256, 2) void k_fc(const float* __restrict__ x,
                                               const float* __restrict__ W,
                                               const float* __restrict__ bias) {
    extern __shared__ float fsm[];

    int tid  = threadIdx.x;
    int lane = tid & 31;
    int wid  = tid >> 5;
    int wm   = wid & 3;           // 4 row-groups of 32
    int wn   = wid >> 2;          // 2 col-groups of 32
    int g    = lane >> 2;
    int t    = lane & 3;
    int m0   = blockIdx.y * 128;
    int n0   = blockIdx.x * 64;

    float acc[2][4][4];
    #pragma unroll
    for (int tm = 0; tm < 2; tm++)
        #pragma unroll
        for (int tn = 0; tn < 4; tn++)
            #pragma unroll
            for (int c = 0; c < 4; c++) acc[tm][tn][c] = 0.0f;

    // load-issue lambda (chunk kc -> buffer b)
    auto issue = [&](int b, int k0) {
        #pragma unroll
        for (int v = 0; v < 4; v++) {          // X: 128x32 = 1024 float4
            int idx = tid + v * 256;
            int row = idx >> 3, c4 = (idx & 7) * 4;
            cp16(&XS(b, row, c4), &x[(m0 + row) * D_IN + k0 + c4]);
        }
        #pragma unroll
        for (int v = 0; v < 2; v++) {          // W: 32x64 = 512 float4
            int idx = tid + v * 256;
            int kr = idx >> 4, c4 = (idx & 15) * 4;
            cp16(&WS(b, kr, c4), &W[(k0 + kr) * D_OUT + n0 + c4]);
        }
        CP_COMMIT();
    };

    issue(0, 0);
    for (int kc = 0; kc < D_IN / FC_BK; kc++) {
        int cur = kc & 1;
        if (kc < D_IN / FC_BK - 1) { issue(cur ^ 1, (kc + 1) * FC_BK); CP_WAIT1(); }
        else                       { CP_WAIT0(); }
        __syncthreads();

        #pragma unroll
        for (int ks = 0; ks < FC_BK / 8; ks++) {
            int kk = ks * 8;
            unsigned ah[2][4], al[2][4], bh[4][2], bl[4][2];
            #pragma unroll
            for (int tm = 0; tm < 2; tm++) {
                int r = wm * 32 + tm * 16 + g;
                float f0 = XS(cur, r,     kk + t);
                float f1 = XS(cur, r + 8, kk + t);
                float f2 = XS(cur, r,     kk + t + 4);
                float f3 = XS(cur, r + 8, kk + t + 4);
                ah[tm][0] = tf32_hi(f0); al[tm][0] = __float_as_uint(f0 - __uint_as_float(ah[tm][0]));
                ah[tm][1] = tf32_hi(f1); al[tm][1] = __float_as_uint(f1 - __uint_as_float(ah[tm][1]));
                ah[tm][2] = tf32_hi(f2); al[tm][2] = __float_as_uint(f2 - __uint_as_float(ah[tm][2]));
                ah[tm][3] = tf32_hi(f3); al[tm][3] = __float_as_uint(f3 - __uint_as_float(ah[tm][3]));
            }
            #pragma unroll
            for (int tn = 0; tn < 4; tn++) {
                int c = wn * 32 + tn * 8 + g;
                float f0 = WS(cur, kk + t,     c);
                float f1 = WS(cur, kk + t + 4, c);
                bh[tn][0] = tf32_hi(f0); bl[tn][0] = __float_as_uint(f0 - __uint_as_float(bh[tn][0]));
                bh[tn][1] = tf32_hi(f1); bl[tn][1] = __float_as_uint(f1 - __uint_as_float(bh[tn][1]));
            }
            #pragma unroll
            for (int tm = 0; tm < 2; tm++)
                #pragma unroll
                for (int tn = 0; tn < 4; tn++) {
                    mma_tf32(acc[tm][tn], ah[tm], bh[tn]);
                    mma_tf32(acc[tm][tn], ah[tm], bl[tn]);
                    mma_tf32(acc[tm][tn], al[tm], bh[tn]);
                }
        }
        __syncthreads();
    }

    // epilogue: + bias, store h, fused partial ||h_row||^2
    float ssum[4] = {0.0f, 0.0f, 0.0f, 0.0f};
    #pragma unroll
    for (int tn = 0; tn < 4; tn++) {
        int c = n0 + wn * 32 + tn * 8 + 2 * t;
        float b0 = bias[c], b1 = bias[c + 1];
        #pragma unroll
        for (int tm = 0; tm < 2; tm++) {
            int r0 = m0 + wm * 32 + tm * 16 + g;
            float o00 = acc[tm][tn][0] + b0, o01 = acc[tm][tn][1] + b1;
            float o10 = acc[tm][tn][2] + b0, o11 = acc[tm][tn][3] + b1;
            *(float2*)&g_h[r0 * D_OUT + c]       = make_float2(o00, o01);
            *(float2*)&g_h[(r0 + 8) * D_OUT + c] = make_float2(o10, o11);
            ssum[tm * 2 + 0] += o00 * o00 + o01 * o01;
            ssum[tm * 2 + 1] += o10 * o10 + o11 * o11;
        }
    }
    #pragma unroll
    for (int rr = 0; rr < 4; rr++) {
        float s = ssum[rr];
        s += __shfl_xor_sync(0xffffffffu, s, 1);
        s += __shfl_xor_sync(0xffffffffu, s, 2);
        if (t == 0) {
            int r = m0 + wm * 32 + (rr >> 1) * 16 + (rr & 1) * 8 + g;
            atomicAdd(&g_sq[r], s);
        }
    }
}

// ---------------- kernel 3: Gram via tf32 mma + hardest pos/neg -------------
// 128x128 block tile, BK=32, double-buffered cp.async pipeline.
#define D_BK   32
#define D_TW   (128 * 36)           // one A or B buffer, words
#define D_SMEM ((4 * D_TW + 128 + 128) * 4)

#define AS(b, r, c) dsm[(b) * D_TW + (r) * 36 + (c)]
#define BS(b, r, c) dsm[2 * D_TW + (b) * D_TW + (r) * 36 + (c)]

__global__ __launch_bounds__(256, 2) void k_dist(const void* __restrict__ targets) {
    extern __shared__ float dsm[];
    float* s_sq = &dsm[4 * D_TW];
    int*   s_cl = (int*)&dsm[4 * D_TW + 128];

    int tid  = threadIdx.x;
    int lane = tid & 31;
    int wid  = tid >> 5;
    int wm   = wid & 3;          // 4 row-groups of 32
    int wn   = wid >> 2;         // 2 col-groups of 64
    int g    = lane >> 2;
    int t    = lane & 3;
    int i0   = blockIdx.x * 128;
    int is64 = g_is64;

    int ci4[4];
    #pragma unroll
    for (int r = 0; r < 4; r++)
        ci4[r] = get_cls(targets, i0 + wm * 32 + (r >> 1) * 16 + (r & 1) * 8 + g, is64);

    float mp[4], mn[4];
    #pragma unroll
    for (int r = 0; r < 4; r++) { mp[r] = -CUDART_INF_F; mn[r] = CUDART_INF_F; }

    for (int jt = blockIdx.y; jt < 32; jt += 8) {
        int j0 = jt * 128;

        float acc[2][8][4];
        #pragma unroll
        for (int tm = 0; tm < 2; tm++)
            #pragma unroll
            for (int tn = 0; tn < 8; tn++)
                #pragma unroll
                for (int c = 0; c < 4; c++) acc[tm][tn][c] = 0.0f;

        auto issue = [&](int b, int k0) {
            #pragma unroll
            for (int v = 0; v < 4; v++) {
                int idx = tid + v * 256;
                int row = idx >> 3, c4 = (idx & 7) * 4;
                cp16(&AS(b, row, c4), &g_h[(i0 + row) * D_OUT + k0 + c4]);
                cp16(&BS(b, row, c4), &g_h[(j0 + row) * D_OUT + k0 + c4]);
            }
            CP_COMMIT();
        };

        if (tid < 128) {                 // epilogue metadata (read after many bars)
            s_sq[tid] = g_sq[j0 + tid];
            s_cl[tid] = get_cls(targets, j0 + tid, is64);
        }

        issue(0, 0);
        #pragma unroll
        for (int kc = 0; kc < D_OUT / D_BK; kc++) {
            int cur = kc & 1;
            if (kc < D_OUT / D_BK - 1) { issue(cur ^ 1, (kc + 1) * D_BK); CP_WAIT1(); }
            else                       { CP_WAIT0(); }
            __syncthreads();

            #pragma unroll
            for (int ks = 0; ks < D_BK / 8; ks++) {
                int kk = ks * 8;
                unsigned a[2][4], b[8][2];
                #pragma unroll
                for (int tm = 0; tm < 2; tm++) {
                    int r = wm * 32 + tm * 16 + g;
                    a[tm][0] = __float_as_uint(AS(cur, r,     kk + t));
                    a[tm][1] = __float_as_uint(AS(cur, r + 8, kk + t));
                    a[tm][2] = __float_as_uint(AS(cur, r,     kk + t + 4));
                    a[tm][3] = __float_as_uint(AS(cur, r + 8, kk + t + 4));
                }
                #pragma unroll
                for (int tn = 0; tn < 8; tn++) {
                    int c = wn * 64 + tn * 8 + g;
                    b[tn][0] = __float_as_uint(BS(cur, c, kk + t));
                    b[tn][1] = __float_as_uint(BS(cur, c, kk + t + 4));
                }
                #pragma unroll
                for (int tm = 0; tm < 2; tm++)
                    #pragma unroll
                    for (int tn = 0; tn < 8; tn++)
                        mma_tf32(acc[tm][tn], a[tm], b[tn]);
            }
            __syncthreads();
        }

        #pragma unroll
        for (int tn = 0; tn < 8; tn++) {
            int c = wn * 64 + tn * 8 + 2 * t;
            float sq1 = s_sq[c], sq2 = s_sq[c + 1];
            int   cl1 = s_cl[c], cl2 = s_cl[c + 1];
            #pragma unroll
            for (int tm = 0; tm < 2; tm++) {
                float v00 = fmaf(-2.0f, acc[tm][tn][0], sq1);
                float v01 = fmaf(-2.0f, acc[tm][tn][1], sq2);
                float v10 = fmaf(-2.0f, acc[tm][tn][2], sq1);
                float v11 = fmaf(-2.0f, acc[tm][tn][3], sq2);
                int r0 = tm * 2, r1 = tm * 2 + 1;
                if (ci4[r0] == cl1) mp[r0] = fmaxf(mp[r0], v00); else mn[r0] = fminf(mn[r0], v00);
                if (ci4[r0] == cl2) mp[r0] = fmaxf(mp[r0], v01); else mn[r0] = fminf(mn[r0], v01);
                if (ci4[r1] == cl1) mp[r1] = fmaxf(mp[r1], v10); else mn[r1] = fminf(mn[r1], v10);
                if (ci4[r1] == cl2) mp[r1] = fmaxf(mp[r1], v11); else mn[r1] = fminf(mn[r1], v11);
            }
        }
        __syncthreads();   // s_sq/s_cl rewritten next jt
    }

    #pragma unroll
    for (int r = 0; r < 4; r++) {
        float p = mp[r], q = mn[r];
        #pragma unroll
        for (int o = 2; o; o >>= 1) {
            p = fmaxf(p, __shfl_xor_sync(0xffffffffu, p, o));
            q = fminf(q, __shfl_xor_sync(0xffffffffu, q, o));
        }
        if (t == 0) {
            int i = i0 + wm * 32 + (r >> 1) * 16 + (r & 1) * 8 + g;
            atomicMax(&g_hp[i], enc_f(p));
            atomicMin(&g_hn[i], enc_f(q));
        }
    }
}

// ---------------- kernel 4: loss = sum softplus(hp - hn), 16 blocks ---------
__global__ __launch_bounds__(256) void k_loss(float* __restrict__ out) {
    __shared__ float red[8];
    int i = blockIdx.x * 256 + threadIdx.x;
    float sqi = g_sq[i];
    float hp = sqrtf(fmaxf(sqi + dec_f(g_hp[i]), 0.0f));
    float hn = sqrtf(fmaxf(sqi + dec_f(g_hn[i]), 0.0f));
    float xv = hp - hn;
    float s  = (xv > 20.0f) ? xv : log1pf(expf(xv));
    #pragma unroll
    for (int o = 16; o; o >>= 1) s += __shfl_xor_sync(0xffffffffu, s, o);
    if ((threadIdx.x & 31) == 0) red[threadIdx.x >> 5] = s;
    __syncthreads();
    if (threadIdx.x < 32) {
        float v = (threadIdx.x < 8) ? red[threadIdx.x] : 0.0f;
        #pragma unroll
        for (int o = 4; o; o >>= 1) v += __shfl_xor_sync(0xffffffffu, v, o);
        if (threadIdx.x == 0) atomicAdd(out, v);
    }
}

// ---------------- launch ----------------------------------------------------
extern "C" void kernel_launch(void* const* d_in, const int* in_sizes, int n_in,
                              void* d_out, int out_size) {
    const float* x  = (const float*)d_in[0];
    const float* W  = (const float*)d_in[1];
    const float* b  = (const float*)d_in[2];
    const void*  tg = d_in[3];

    cudaFuncSetAttribute(k_fc,   cudaFuncAttributeMaxDynamicSharedMemorySize, FC_SMEM);
    cudaFuncSetAttribute(k_dist, cudaFuncAttributeMaxDynamicSharedMemorySize, D_SMEM);

    k_init<<<1, 1024>>>((const unsigned*)tg, (float*)d_out);
    k_fc  <<<dim3(D_OUT / 64, N_SAMPLES / 128), 256, FC_SMEM>>>(x, W, b);
    k_dist<<<dim3(N_SAMPLES / 128, 8), 256, D_SMEM>>>(tg);
    k_loss<<<N_SAMPLES / 256, 256>>>((float*)d_out);
}

// round 11
// speedup vs baseline: 5.0904x; 1.2836x over previous
#include <cuda_runtime.h>
#include <math_constants.h>

#define N_SAMPLES 4096
#define D_IN      1024
#define D_OUT     256

// ---------------- persistent device scratch (no allocations allowed) --------
__device__ float    g_h [N_SAMPLES * D_OUT];   // projected features, 4 MB
__device__ float    g_sq[N_SAMPLES];           // ||h_i||^2 (atomic-accumulated)
__device__ unsigned g_hp[N_SAMPLES];           // enc(max over same-class of sq_o-2g)
__device__ unsigned g_hn[N_SAMPLES];           // enc(min over diff-class of sq_o-2g)
__device__ int      g_is64;

__device__ __forceinline__ int get_cls(const void* T, int i, int is64) {
    return is64 ? (int)((const long long*)T)[i] : ((const int*)T)[i];
}

// order-preserving float <-> uint encoding (handles negatives / inf)
__device__ __forceinline__ unsigned enc_f(float f) {
    unsigned b = __float_as_uint(f);
    return (b & 0x80000000u) ? ~b : (b | 0x80000000u);
}
__device__ __forceinline__ float dec_f(unsigned u) {
    return __uint_as_float((u & 0x80000000u) ? (u ^ 0x80000000u) : ~u);
}

// tf32 warp mma: D = A(16x8) * B(8x8) + D, fp32 accumulate
__device__ __forceinline__ void mma_tf32(float* d, const unsigned* a, const unsigned* b) {
    asm volatile(
        "mma.sync.aligned.m16n8k8.row.col.f32.tf32.tf32.f32 "
        "{%0,%1,%2,%3}, {%4,%5,%6,%7}, {%8,%9}, {%0,%1,%2,%3};"
        : "+f"(d[0]), "+f"(d[1]), "+f"(d[2]), "+f"(d[3])
        : "r"(a[0]), "r"(a[1]), "r"(a[2]), "r"(a[3]), "r"(b[0]), "r"(b[1]));
}

__device__ __forceinline__ unsigned tf32_hi(float x) {
    unsigned r;
    asm("cvt.rna.tf32.f32 %0, %1;" : "=r"(r) : "f"(x));
    return r;
}

// cp.async helpers (16B, L2-only .cg path)
__device__ __forceinline__ void cp16(const void* smem_dst, const void* gmem_src) {
    unsigned s = (unsigned)__cvta_generic_to_shared(smem_dst);
    asm volatile("cp.async.cg.shared.global [%0], [%1], 16;" :: "r"(s), "l"(gmem_src));
}
#define CP_COMMIT() asm volatile("cp.async.commit_group;" ::: "memory")
#define CP_WAIT1()  asm volatile("cp.async.wait_group 1;" ::: "memory")
#define CP_WAIT0()  asm volatile("cp.async.wait_group 0;" ::: "memory")

// ---------------- kernel 0: dtype detect + per-launch re-init ---------------
__global__ void k_init(const unsigned* __restrict__ twords, float* __restrict__ out) {
    __shared__ unsigned red[32];
    int tid = threadIdx.x;
    unsigned acc = 0;
    for (int i = tid; i < 2048; i += 1024) acc |= twords[2 * i + 1];
    #pragma unroll
    for (int o = 16; o; o >>= 1) acc |= __shfl_xor_sync(0xffffffffu, acc, o);
    if ((tid & 31) == 0) red[tid >> 5] = acc;
    __syncthreads();
    if (tid < 32) {
        unsigned v = red[tid];
        #pragma unroll
        for (int o = 16; o; o >>= 1) v |= __shfl_xor_sync(0xffffffffu, v, o);
        if (tid == 0) g_is64 = (v == 0u) ? 1 : 0;
    }
    if (tid == 0) out[0] = 0.0f;
    for (int i = tid; i < N_SAMPLES; i += 1024) {
        g_hp[i] = 0u;
        g_hn[i] = 0xffffffffu;
        g_sq[i] = 0.0f;
    }
}

// ---------------- kernel 1: h = x @ W + b via 3xTF32 mma, fused ||h||^2 -----
#define FC_BK   32
#define FC_XW   (128 * 36)
#define FC_WW   (FC_BK * 72)
#define FC_SMEM ((2 * FC_XW + 2 * FC_WW) * 4)

#define XS(b, r, c) fsm[(b) * FC_XW + (r) * 36 + (c)]
#define WS(b, k, c) fsm[2 * FC_XW + (b) * FC_WW + (k) * 72 + (c)]

__global__ __launch_bounds__(256, 2) void k_fc(const float* __restrict__ x,
                                               const float* __restrict__ W,
                                               const float* __restrict__ bias) {
    extern __shared__ float fsm[];

    int tid  = threadIdx.x;
    int lane = tid & 31;
    int wid  = tid >> 5;
    int wm   = wid & 3;
    int wn   = wid >> 2;
    int g    = lane >> 2;
    int t    = lane & 3;
    int m0   = blockIdx.y * 128;
    int n0   = blockIdx.x * 64;

    float acc[2][4][4];
    #pragma unroll
    for (int tm = 0; tm < 2; tm++)
        #pragma unroll
        for (int tn = 0; tn < 4; tn++)
            #pragma unroll
            for (int c = 0; c < 4; c++) acc[tm][tn][c] = 0.0f;

    auto issue = [&](int b, int k0) {
        #pragma unroll
        for (int v = 0; v < 4; v++) {
            int idx = tid + v * 256;
            int row = idx >> 3, c4 = (idx & 7) * 4;
            cp16(&XS(b, row, c4), &x[(m0 + row) * D_IN + k0 + c4]);
        }
        #pragma unroll
        for (int v = 0; v < 2; v++) {
            int idx = tid + v * 256;
            int kr = idx >> 4, c4 = (idx & 15) * 4;
            cp16(&WS(b, kr, c4), &W[(k0 + kr) * D_OUT + n0 + c4]);
        }
        CP_COMMIT();
    };

    issue(0, 0);
    for (int kc = 0; kc < D_IN / FC_BK; kc++) {
        int cur = kc & 1;
        if (kc < D_IN / FC_BK - 1) { issue(cur ^ 1, (kc + 1) * FC_BK); CP_WAIT1(); }
        else                       { CP_WAIT0(); }
        __syncthreads();

        #pragma unroll
        for (int ks = 0; ks < FC_BK / 8; ks++) {
            int kk = ks * 8;
            unsigned ah[2][4], al[2][4], bh[4][2], bl[4][2];
            #pragma unroll
            for (int tm = 0; tm < 2; tm++) {
                int r = wm * 32 + tm * 16 + g;
                float f0 = XS(cur, r,     kk + t);
                float f1 = XS(cur, r + 8, kk + t);
                float f2 = XS(cur, r,     kk + t + 4);
                float f3 = XS(cur, r + 8, kk + t + 4);
                ah[tm][0] = tf32_hi(f0); al[tm][0] = __float_as_uint(f0 - __uint_as_float(ah[tm][0]));
                ah[tm][1] = tf32_hi(f1); al[tm][1] = __float_as_uint(f1 - __uint_as_float(ah[tm][1]));
                ah[tm][2] = tf32_hi(f2); al[tm][2] = __float_as_uint(f2 - __uint_as_float(ah[tm][2]));
                ah[tm][3] = tf32_hi(f3); al[tm][3] = __float_as_uint(f3 - __uint_as_float(ah[tm][3]));
            }
            #pragma unroll
            for (int tn = 0; tn < 4; tn++) {
                int c = wn * 32 + tn * 8 + g;
                float f0 = WS(cur, kk + t,     c);
                float f1 = WS(cur, kk + t + 4, c);
                bh[tn][0] = tf32_hi(f0); bl[tn][0] = __float_as_uint(f0 - __uint_as_float(bh[tn][0]));
                bh[tn][1] = tf32_hi(f1); bl[tn][1] = __float_as_uint(f1 - __uint_as_float(bh[tn][1]));
            }
            #pragma unroll
            for (int tm = 0; tm < 2; tm++)
                #pragma unroll
                for (int tn = 0; tn < 4; tn++) {
                    mma_tf32(acc[tm][tn], ah[tm], bh[tn]);
                    mma_tf32(acc[tm][tn], ah[tm], bl[tn]);
                    mma_tf32(acc[tm][tn], al[tm], bh[tn]);
                }
        }
        __syncthreads();
    }

    float ssum[4] = {0.0f, 0.0f, 0.0f, 0.0f};
    #pragma unroll
    for (int tn = 0; tn < 4; tn++) {
        int c = n0 + wn * 32 + tn * 8 + 2 * t;
        float b0 = bias[c], b1 = bias[c + 1];
        #pragma unroll
        for (int tm = 0; tm < 2; tm++) {
            int r0 = m0 + wm * 32 + tm * 16 + g;
            float o00 = acc[tm][tn][0] + b0, o01 = acc[tm][tn][1] + b1;
            float o10 = acc[tm][tn][2] + b0, o11 = acc[tm][tn][3] + b1;
            *(float2*)&g_h[r0 * D_OUT + c]       = make_float2(o00, o01);
            *(float2*)&g_h[(r0 + 8) * D_OUT + c] = make_float2(o10, o11);
            ssum[tm * 2 + 0] += o00 * o00 + o01 * o01;
            ssum[tm * 2 + 1] += o10 * o10 + o11 * o11;
        }
    }
    #pragma unroll
    for (int rr = 0; rr < 4; rr++) {
        float s = ssum[rr];
        s += __shfl_xor_sync(0xffffffffu, s, 1);
        s += __shfl_xor_sync(0xffffffffu, s, 2);
        if (t == 0) {
            int r = m0 + wm * 32 + (rr >> 1) * 16 + (rr & 1) * 8 + g;
            atomicAdd(&g_sq[r], s);
        }
    }
}

// ---------------- kernel 3: symmetric Gram, tf32 mma, dual-direction --------
// Only tiles with jt >= it are computed (528 of 1024). Each tile feeds BOTH
// the i-row reduction (val = sq_j - 2g) and, off-diagonal, the j-row
// reduction (val = sq_i - 2g). sqrt + own-sq deferred to k_loss.
#define D_BK   32
#define D_TW   (128 * 36)
#define D_SMEM ((4 * D_TW + 128 + 128) * 4)

#define AS(b, r, c) dsm[(b) * D_TW + (r) * 36 + (c)]
#define BS(b, r, c) dsm[2 * D_TW + (b) * D_TW + (r) * 36 + (c)]

__global__ __launch_bounds__(256, 2) void k_dist(const void* __restrict__ targets) {
    int it = blockIdx.x, jt = blockIdx.y;
    if (jt < it) return;                       // lower triangle: symmetric, skip
    bool do_T = (jt != it);                    // diagonal: normal pass covers all

    extern __shared__ float dsm[];
    float* s_sq = &dsm[4 * D_TW];
    int*   s_cl = (int*)&dsm[4 * D_TW + 128];

    int tid  = threadIdx.x;
    int lane = tid & 31;
    int wid  = tid >> 5;
    int wm   = wid & 3;          // 4 row-groups of 32
    int wn   = wid >> 2;         // 2 col-groups of 64
    int g    = lane >> 2;
    int t    = lane & 3;
    int i0   = it * 128;
    int j0   = jt * 128;
    int is64 = g_is64;

    int   ci4[4];
    float sqi4[4];
    #pragma unroll
    for (int r = 0; r < 4; r++) {
        int i  = i0 + wm * 32 + (r >> 1) * 16 + (r & 1) * 8 + g;
        ci4[r]  = get_cls(targets, i, is64);
        sqi4[r] = g_sq[i];
    }

    float mp[4], mn[4];
    #pragma unroll
    for (int r = 0; r < 4; r++) { mp[r] = -CUDART_INF_F; mn[r] = CUDART_INF_F; }

    float acc[2][8][4];
    #pragma unroll
    for (int tm = 0; tm < 2; tm++)
        #pragma unroll
        for (int tn = 0; tn < 8; tn++)
            #pragma unroll
            for (int c = 0; c < 4; c++) acc[tm][tn][c] = 0.0f;

    auto issue = [&](int b, int k0) {
        #pragma unroll
        for (int v = 0; v < 4; v++) {
            int idx = tid + v * 256;
            int row = idx >> 3, c4 = (idx & 7) * 4;
            cp16(&AS(b, row, c4), &g_h[(i0 + row) * D_OUT + k0 + c4]);
            cp16(&BS(b, row, c4), &g_h[(j0 + row) * D_OUT + k0 + c4]);
        }
        CP_COMMIT();
    };

    if (tid < 128) {
        s_sq[tid] = g_sq[j0 + tid];
        s_cl[tid] = get_cls(targets, j0 + tid, is64);
    }

    issue(0, 0);
    #pragma unroll
    for (int kc = 0; kc < D_OUT / D_BK; kc++) {
        int cur = kc & 1;
        if (kc < D_OUT / D_BK - 1) { issue(cur ^ 1, (kc + 1) * D_BK); CP_WAIT1(); }
        else                       { CP_WAIT0(); }
        __syncthreads();

        #pragma unroll
        for (int ks = 0; ks < D_BK / 8; ks++) {
            int kk = ks * 8;
            unsigned a[2][4], b[8][2];
            #pragma unroll
            for (int tm = 0; tm < 2; tm++) {
                int r = wm * 32 + tm * 16 + g;
                a[tm][0] = __float_as_uint(AS(cur, r,     kk + t));
                a[tm][1] = __float_as_uint(AS(cur, r + 8, kk + t));
                a[tm][2] = __float_as_uint(AS(cur, r,     kk + t + 4));
                a[tm][3] = __float_as_uint(AS(cur, r + 8, kk + t + 4));
            }
            #pragma unroll
            for (int tn = 0; tn < 8; tn++) {
                int c = wn * 64 + tn * 8 + g;
                b[tn][0] = __float_as_uint(BS(cur, c, kk + t));
                b[tn][1] = __float_as_uint(BS(cur, c, kk + t + 4));
            }
            #pragma unroll
            for (int tm = 0; tm < 2; tm++)
                #pragma unroll
                for (int tn = 0; tn < 8; tn++)
                    mma_tf32(acc[tm][tn], a[tm], b[tn]);
        }
        __syncthreads();
    }

    // epilogue: normal direction (rows i) + transposed direction (rows j)
    #pragma unroll
    for (int tn = 0; tn < 8; tn++) {
        int cc = wn * 64 + tn * 8 + 2 * t;
        float sq1 = s_sq[cc], sq2 = s_sq[cc + 1];
        int   cl1 = s_cl[cc], cl2 = s_cl[cc + 1];
        float tp0 = -CUDART_INF_F, tq0 = CUDART_INF_F;   // j = cc
        float tp1 = -CUDART_INF_F, tq1 = CUDART_INF_F;   // j = cc+1
        #pragma unroll
        for (int tm = 0; tm < 2; tm++) {
            float a00 = acc[tm][tn][0], a01 = acc[tm][tn][1];
            float a10 = acc[tm][tn][2], a11 = acc[tm][tn][3];
            int r0 = tm * 2, r1 = tm * 2 + 1;
            // normal: val = sq_j - 2g, keyed to row i
            float v00 = fmaf(-2.0f, a00, sq1);
            float v01 = fmaf(-2.0f, a01, sq2);
            float v10 = fmaf(-2.0f, a10, sq1);
            float v11 = fmaf(-2.0f, a11, sq2);
            if (ci4[r0] == cl1) mp[r0] = fmaxf(mp[r0], v00); else mn[r0] = fminf(mn[r0], v00);
            if (ci4[r0] == cl2) mp[r0] = fmaxf(mp[r0], v01); else mn[r0] = fminf(mn[r0], v01);
            if (ci4[r1] == cl1) mp[r1] = fmaxf(mp[r1], v10); else mn[r1] = fminf(mn[r1], v10);
            if (ci4[r1] == cl2) mp[r1] = fmaxf(mp[r1], v11); else mn[r1] = fminf(mn[r1], v11);
            if (do_T) {
                // transposed: val = sq_i - 2g, keyed to row j
                float w00 = fmaf(-2.0f, a00, sqi4[r0]);
                float w01 = fmaf(-2.0f, a01, sqi4[r0]);
                float w10 = fmaf(-2.0f, a10, sqi4[r1]);
                float w11 = fmaf(-2.0f, a11, sqi4[r1]);
                if (ci4[r0] == cl1) tp0 = fmaxf(tp0, w00); else tq0 = fminf(tq0, w00);
                if (ci4[r0] == cl2) tp1 = fmaxf(tp1, w01); else tq1 = fminf(tq1, w01);
                if (ci4[r1] == cl1) tp0 = fmaxf(tp0, w10); else tq0 = fminf(tq0, w10);
                if (ci4[r1] == cl2) tp1 = fmaxf(tp1, w11); else tq1 = fminf(tq1, w11);
            }
        }
        if (do_T) {
            // reduce over g (lanes stride 4 share (t, tn) => same j columns)
            #pragma unroll
            for (int o = 4; o <= 16; o <<= 1) {
                tp0 = fmaxf(tp0, __shfl_xor_sync(0xffffffffu, tp0, o));
                tq0 = fminf(tq0, __shfl_xor_sync(0xffffffffu, tq0, o));
                tp1 = fmaxf(tp1, __shfl_xor_sync(0xffffffffu, tp1, o));
                tq1 = fminf(tq1, __shfl_xor_sync(0xffffffffu, tq1, o));
            }
            if (g == 0) {
                atomicMax(&g_hp[j0 + cc],     enc_f(tp0));
                atomicMin(&g_hn[j0 + cc],     enc_f(tq0));
                atomicMax(&g_hp[j0 + cc + 1], enc_f(tp1));
                atomicMin(&g_hn[j0 + cc + 1], enc_f(tq1));
            }
        }
    }

    #pragma unroll
    for (int r = 0; r < 4; r++) {
        float p = mp[r], q = mn[r];
        #pragma unroll
        for (int o = 2; o; o >>= 1) {
            p = fmaxf(p, __shfl_xor_sync(0xffffffffu, p, o));
            q = fminf(q, __shfl_xor_sync(0xffffffffu, q, o));
        }
        if (t == 0) {
            int i = i0 + wm * 32 + (r >> 1) * 16 + (r & 1) * 8 + g;
            atomicMax(&g_hp[i], enc_f(p));
            atomicMin(&g_hn[i], enc_f(q));
        }
    }
}

// ---------------- kernel 4: loss = sum softplus(hp - hn), 16 blocks ---------
__global__ __launch_bounds__(256) void k_loss(float* __restrict__ out) {
    __shared__ float red[8];
    int i = blockIdx.x * 256 + threadIdx.x;
    float sqi = g_sq[i];
    float hp = sqrtf(fmaxf(sqi + dec_f(g_hp[i]), 0.0f));
    float hn = sqrtf(fmaxf(sqi + dec_f(g_hn[i]), 0.0f));
    float xv = hp - hn;
    float s  = (xv > 20.0f) ? xv : log1pf(expf(xv));
    #pragma unroll
    for (int o = 16; o; o >>= 1) s += __shfl_xor_sync(0xffffffffu, s, o);
    if ((threadIdx.x & 31) == 0) red[threadIdx.x >> 5] = s;
    __syncthreads();
    if (threadIdx.x < 32) {
        float v = (threadIdx.x < 8) ? red[threadIdx.x] : 0.0f;
        #pragma unroll
        for (int o = 4; o; o >>= 1) v += __shfl_xor_sync(0xffffffffu, v, o);
        if (threadIdx.x == 0) atomicAdd(out, v);
    }
}

// ---------------- launch ----------------------------------------------------
extern "C" void kernel_launch(void* const* d_in, const int* in_sizes, int n_in,
                              void* d_out, int out_size) {
    const float* x  = (const float*)d_in[0];
    const float* W  = (const float*)d_in[1];
    const float* b  = (const float*)d_in[2];
    const void*  tg = d_in[3];

    cudaFuncSetAttribute(k_fc,   cudaFuncAttributeMaxDynamicSharedMemorySize, FC_SMEM);
    cudaFuncSetAttribute(k_dist, cudaFuncAttributeMaxDynamicSharedMemorySize, D_SMEM);

    k_init<<<1, 1024>>>((const unsigned*)tg, (float*)d_out);
    k_fc  <<<dim3(D_OUT / 64, N_SAMPLES / 128), 256, FC_SMEM>>>(x, W, b);
    k_dist<<<dim3(32, 32), 256, D_SMEM>>>(tg);
    k_loss<<<N_SAMPLES / 256, 256>>>((float*)d_out);
}

// round 12
// speedup vs baseline: 5.4002x; 1.0609x over previous
#include <cuda_runtime.h>
#include <math_constants.h>

#define N_SAMPLES 4096
#define D_IN      1024
#define D_OUT     256

// ---------------- persistent device scratch (no allocations allowed) --------
__device__ float    g_h [N_SAMPLES * D_OUT];   // projected features, 4 MB
__device__ float    g_sq[N_SAMPLES];           // ||h_i||^2 (atomic-accumulated)
__device__ unsigned g_hp[N_SAMPLES];           // enc(max over same-class of sq_o-2g)
__device__ unsigned g_hn[N_SAMPLES];           // enc(min over diff-class of sq_o-2g)
__device__ int      g_is64;

__device__ __forceinline__ int get_cls(const void* T, int i, int is64) {
    return is64 ? (int)((const long long*)T)[i] : ((const int*)T)[i];
}

// order-preserving float <-> uint encoding (handles negatives / inf)
__device__ __forceinline__ unsigned enc_f(float f) {
    unsigned b = __float_as_uint(f);
    return (b & 0x80000000u) ? ~b : (b | 0x80000000u);
}
__device__ __forceinline__ float dec_f(unsigned u) {
    return __uint_as_float((u & 0x80000000u) ? (u ^ 0x80000000u) : ~u);
}

// tf32 warp mma: D = A(16x8) * B(8x8) + D, fp32 accumulate
__device__ __forceinline__ void mma_tf32(float* d, const unsigned* a,
                                         unsigned b0, unsigned b1) {
    asm volatile(
        "mma.sync.aligned.m16n8k8.row.col.f32.tf32.tf32.f32 "
        "{%0,%1,%2,%3}, {%4,%5,%6,%7}, {%8,%9}, {%0,%1,%2,%3};"
        : "+f"(d[0]), "+f"(d[1]), "+f"(d[2]), "+f"(d[3])
        : "r"(a[0]), "r"(a[1]), "r"(a[2]), "r"(a[3]), "r"(b0), "r"(b1));
}

__device__ __forceinline__ unsigned tf32_hi(float x) {
    unsigned r;
    asm("cvt.rna.tf32.f32 %0, %1;" : "=r"(r) : "f"(x));
    return r;
}

// ldmatrix x4: four 8-row x 16B tiles, lane L provides row addr; lane L
// receives word (L%4) of row (L/4) of tile (L/8)  -> tf32 fragment layout.
__device__ __forceinline__ void ldsm4(unsigned* r, unsigned addr) {
    asm volatile("ldmatrix.sync.aligned.m8n8.x4.shared.b16 {%0,%1,%2,%3}, [%4];"
                 : "=r"(r[0]), "=r"(r[1]), "=r"(r[2]), "=r"(r[3]) : "r"(addr));
}

// cp.async helpers (16B, L2-only .cg path)
__device__ __forceinline__ void cp16(const void* smem_dst, const void* gmem_src) {
    unsigned s = (unsigned)__cvta_generic_to_shared(smem_dst);
    asm volatile("cp.async.cg.shared.global [%0], [%1], 16;" :: "r"(s), "l"(gmem_src));
}
#define CP_COMMIT() asm volatile("cp.async.commit_group;" ::: "memory")
#define CP_WAIT1()  asm volatile("cp.async.wait_group 1;" ::: "memory")
#define CP_WAIT0()  asm volatile("cp.async.wait_group 0;" ::: "memory")

// ---------------- kernel 0: dtype detect + per-launch re-init ---------------
__global__ void k_init(const unsigned* __restrict__ twords, float* __restrict__ out) {
    __shared__ unsigned red[32];
    int tid = threadIdx.x;
    unsigned acc = 0;
    for (int i = tid; i < 2048; i += 1024) acc |= twords[2 * i + 1];
    #pragma unroll
    for (int o = 16; o; o >>= 1) acc |= __shfl_xor_sync(0xffffffffu, acc, o);
    if ((tid & 31) == 0) red[tid >> 5] = acc;
    __syncthreads();
    if (tid < 32) {
        unsigned v = red[tid];
        #pragma unroll
        for (int o = 16; o; o >>= 1) v |= __shfl_xor_sync(0xffffffffu, v, o);
        if (tid == 0) g_is64 = (v == 0u) ? 1 : 0;
    }
    if (tid == 0) out[0] = 0.0f;
    for (int i = tid; i < N_SAMPLES; i += 1024) {
        g_hp[i] = 0u;
        g_hn[i] = 0xffffffffu;
        g_sq[i] = 0.0f;
    }
}

// ---------------- kernel 1: h = x @ W + b via 3xTF32 mma, fused ||h||^2 -----
#define FC_BK   32
#define FC_XW   (128 * 36)
#define FC_WW   (FC_BK * 72)
#define FC_SMEM ((2 * FC_XW + 2 * FC_WW) * 4)

#define XS(b, r, c) fsm[(b) * FC_XW + (r) * 36 + (c)]
#define WS(b, k, c) fsm[2 * FC_XW + (b) * FC_WW + (k) * 72 + (c)]

__global__ __launch_bounds__(256, 2) void k_fc(const float* __restrict__ x,
                                               const float* __restrict__ W,
                                               const float* __restrict__ bias) {
    extern __shared__ float fsm[];
    unsigned sbase = (unsigned)__cvta_generic_to_shared(fsm);

    int tid  = threadIdx.x;
    int lane = tid & 31;
    int wid  = tid >> 5;
    int wm   = wid & 3;
    int wn   = wid >> 2;
    int g    = lane >> 2;
    int t    = lane & 3;
    int m0   = blockIdx.y * 128;
    int n0   = blockIdx.x * 64;
    int l7   = lane & 7;

    // ldmatrix lane row-offsets for X fragments (word units, buf 0, kk=0)
    int aoff[2];
    #pragma unroll
    for (int tm = 0; tm < 2; tm++)
        aoff[tm] = (wm * 32 + tm * 16 + ((lane >> 3) & 1) * 8 + l7) * 36 + (lane >> 4) * 4;

    float acc[2][4][4];
    #pragma unroll
    for (int tm = 0; tm < 2; tm++)
        #pragma unroll
        for (int tn = 0; tn < 4; tn++)
            #pragma unroll
            for (int c = 0; c < 4; c++) acc[tm][tn][c] = 0.0f;

    auto issue = [&](int b, int k0) {
        #pragma unroll
        for (int v = 0; v < 4; v++) {
            int idx = tid + v * 256;
            int row = idx >> 3, c4 = (idx & 7) * 4;
            cp16(&XS(b, row, c4), &x[(m0 + row) * D_IN + k0 + c4]);
        }
        #pragma unroll
        for (int v = 0; v < 2; v++) {
            int idx = tid + v * 256;
            int kr = idx >> 4, c4 = (idx & 15) * 4;
            cp16(&WS(b, kr, c4), &W[(k0 + kr) * D_OUT + n0 + c4]);
        }
        CP_COMMIT();
    };

    issue(0, 0);
    for (int kc = 0; kc < D_IN / FC_BK; kc++) {
        int cur = kc & 1;
        if (kc < D_IN / FC_BK - 1) { issue(cur ^ 1, (kc + 1) * FC_BK); CP_WAIT1(); }
        else                       { CP_WAIT0(); }
        __syncthreads();

        #pragma unroll
        for (int ks = 0; ks < FC_BK / 8; ks++) {
            int kk = ks * 8;
            unsigned ah[2][4], al[2][4], bh[4][2], bl[4][2];
            #pragma unroll
            for (int tm = 0; tm < 2; tm++) {
                unsigned af[4];
                ldsm4(af, sbase + (unsigned)(cur * FC_XW + aoff[tm] + kk) * 4u);
                #pragma unroll
                for (int q = 0; q < 4; q++) {
                    float f = __uint_as_float(af[q]);
                    ah[tm][q] = tf32_hi(f);
                    al[tm][q] = __float_as_uint(f - __uint_as_float(ah[tm][q]));
                }
            }
            #pragma unroll
            for (int tn = 0; tn < 4; tn++) {
                int c = wn * 32 + tn * 8 + g;
                float f0 = WS(cur, kk + t,     c);
                float f1 = WS(cur, kk + t + 4, c);
                bh[tn][0] = tf32_hi(f0); bl[tn][0] = __float_as_uint(f0 - __uint_as_float(bh[tn][0]));
                bh[tn][1] = tf32_hi(f1); bl[tn][1] = __float_as_uint(f1 - __uint_as_float(bh[tn][1]));
            }
            #pragma unroll
            for (int tm = 0; tm < 2; tm++)
                #pragma unroll
                for (int tn = 0; tn < 4; tn++) {
                    mma_tf32(acc[tm][tn], ah[tm], bh[tn][0], bh[tn][1]);
                    mma_tf32(acc[tm][tn], ah[tm], bl[tn][0], bl[tn][1]);
                    mma_tf32(acc[tm][tn], al[tm], bh[tn][0], bh[tn][1]);
                }
        }
        __syncthreads();
    }

    float ssum[4] = {0.0f, 0.0f, 0.0f, 0.0f};
    #pragma unroll
    for (int tn = 0; tn < 4; tn++) {
        int c = n0 + wn * 32 + tn * 8 + 2 * t;
        float b0 = bias[c], b1 = bias[c + 1];
        #pragma unroll
        for (int tm = 0; tm < 2; tm++) {
            int r0 = m0 + wm * 32 + tm * 16 + g;
            float o00 = acc[tm][tn][0] + b0, o01 = acc[tm][tn][1] + b1;
            float o10 = acc[tm][tn][2] + b0, o11 = acc[tm][tn][3] + b1;
            *(float2*)&g_h[r0 * D_OUT + c]       = make_float2(o00, o01);
            *(float2*)&g_h[(r0 + 8) * D_OUT + c] = make_float2(o10, o11);
            ssum[tm * 2 + 0] += o00 * o00 + o01 * o01;
            ssum[tm * 2 + 1] += o10 * o10 + o11 * o11;
        }
    }
    #pragma unroll
    for (int rr = 0; rr < 4; rr++) {
        float s = ssum[rr];
        s += __shfl_xor_sync(0xffffffffu, s, 1);
        s += __shfl_xor_sync(0xffffffffu, s, 2);
        if (t == 0) {
            int r = m0 + wm * 32 + (rr >> 1) * 16 + (rr & 1) * 8 + g;
            atomicAdd(&g_sq[r], s);
        }
    }
}

// ---------------- kernel 3: symmetric Gram, tf32 mma + ldmatrix -------------
// 264 blocks x 2 linearized upper-triangle tiles (528 tiles of 128x128).
// Each tile feeds BOTH the i-row reduction (val = sq_j - 2g) and, off-diag,
// the j-row reduction (val = sq_i - 2g). sqrt + own-sq deferred to k_loss.
#define D_BK   32
#define D_TW   (128 * 36)
#define D_SMEM ((4 * D_TW + 128 + 128) * 4)

#define AS(b, r, c) dsm[(b) * D_TW + (r) * 36 + (c)]
#define BS(b, r, c) dsm[2 * D_TW + (b) * D_TW + (r) * 36 + (c)]

__global__ __launch_bounds__(256, 2) void k_dist(const void* __restrict__ targets) {
    extern __shared__ float dsm[];
    float*   s_sq  = &dsm[4 * D_TW];
    int*     s_cl  = (int*)&dsm[4 * D_TW + 128];
    unsigned sbase = (unsigned)__cvta_generic_to_shared(dsm);

    int tid  = threadIdx.x;
    int lane = tid & 31;
    int wid  = tid >> 5;
    int wm   = wid & 3;          // 4 row-groups of 32
    int wn   = wid >> 2;         // 2 col-groups of 64
    int g    = lane >> 2;
    int t    = lane & 3;
    int is64 = g_is64;
    int l7   = lane & 7;

    // ldmatrix lane offsets (word units, buffer 0, kk=0)
    int aoff[2], boff[4];
    #pragma unroll
    for (int tm = 0; tm < 2; tm++)
        aoff[tm] = (wm * 32 + tm * 16 + ((lane >> 3) & 1) * 8 + l7) * 36 + (lane >> 4) * 4;
    #pragma unroll
    for (int tp = 0; tp < 4; tp++)
        boff[tp] = 2 * D_TW + (wn * 64 + tp * 16 + ((lane >> 4) & 1) * 8 + l7) * 36
                 + ((lane >> 3) & 1) * 4;

    for (int ui = 0; ui < 2; ui++) {
        int u = blockIdx.x * 2 + ui;
        // decode linear index -> (jt >= it) tile coords
        int row = (int)((sqrtf(8.0f * (float)u + 1.0f) - 1.0f) * 0.5f);
        while ((row + 1) * (row + 2) / 2 <= u) row++;
        while (row * (row + 1) / 2 > u) row--;
        int jt = row, it = u - row * (row + 1) / 2;
        bool do_T = (jt != it);
        int i0 = it * 128, j0 = jt * 128;

        if (ui) __syncthreads();             // s_sq/s_cl + smem reuse
        if (tid < 128) {
            s_sq[tid] = g_sq[j0 + tid];
            s_cl[tid] = get_cls(targets, j0 + tid, is64);
        }

        int   ci4[4];
        float sqi4[4];
        #pragma unroll
        for (int r = 0; r < 4; r++) {
            int i   = i0 + wm * 32 + (r >> 1) * 16 + (r & 1) * 8 + g;
            ci4[r]  = get_cls(targets, i, is64);
            sqi4[r] = g_sq[i];
        }

        float acc[2][8][4];
        #pragma unroll
        for (int tm = 0; tm < 2; tm++)
            #pragma unroll
            for (int tn = 0; tn < 8; tn++)
                #pragma unroll
                for (int c = 0; c < 4; c++) acc[tm][tn][c] = 0.0f;

        auto issue = [&](int b, int k0) {
            #pragma unroll
            for (int v = 0; v < 4; v++) {
                int idx = tid + v * 256;
                int rr = idx >> 3, c4 = (idx & 7) * 4;
                cp16(&AS(b, rr, c4), &g_h[(i0 + rr) * D_OUT + k0 + c4]);
                cp16(&BS(b, rr, c4), &g_h[(j0 + rr) * D_OUT + k0 + c4]);
            }
            CP_COMMIT();
        };

        issue(0, 0);
        #pragma unroll
        for (int kc = 0; kc < D_OUT / D_BK; kc++) {
            int cur = kc & 1;
            if (kc < D_OUT / D_BK - 1) { issue(cur ^ 1, (kc + 1) * D_BK); CP_WAIT1(); }
            else                       { CP_WAIT0(); }
            __syncthreads();

            #pragma unroll
            for (int ks = 0; ks < D_BK / 8; ks++) {
                int kk = ks * 8;
                unsigned a[2][4], b[4][4];
                #pragma unroll
                for (int tm = 0; tm < 2; tm++)
                    ldsm4(a[tm], sbase + (unsigned)(cur * D_TW + aoff[tm] + kk) * 4u);
                #pragma unroll
                for (int tp = 0; tp < 4; tp++)
                    ldsm4(b[tp], sbase + (unsigned)(cur * D_TW + boff[tp] + kk) * 4u);
                // b[tp] = { b_{2tp}[0], b_{2tp}[1], b_{2tp+1}[0], b_{2tp+1}[1] }
                #pragma unroll
                for (int tm = 0; tm < 2; tm++)
                    #pragma unroll
                    for (int tn = 0; tn < 8; tn++)
                        mma_tf32(acc[tm][tn], a[tm],
                                 b[tn >> 1][(tn & 1) * 2], b[tn >> 1][(tn & 1) * 2 + 1]);
            }
            __syncthreads();
        }

        float mp[4], mn[4];
        #pragma unroll
        for (int r = 0; r < 4; r++) { mp[r] = -CUDART_INF_F; mn[r] = CUDART_INF_F; }

        #pragma unroll
        for (int tn = 0; tn < 8; tn++) {
            int cc = wn * 64 + tn * 8 + 2 * t;
            float sq1 = s_sq[cc], sq2 = s_sq[cc + 1];
            int   cl1 = s_cl[cc], cl2 = s_cl[cc + 1];
            float tp0 = -CUDART_INF_F, tq0 = CUDART_INF_F;
            float tp1 = -CUDART_INF_F, tq1 = CUDART_INF_F;
            #pragma unroll
            for (int tm = 0; tm < 2; tm++) {
                float a00 = acc[tm][tn][0], a01 = acc[tm][tn][1];
                float a10 = acc[tm][tn][2], a11 = acc[tm][tn][3];
                int r0 = tm * 2, r1 = tm * 2 + 1;
                float v00 = fmaf(-2.0f, a00, sq1);
                float v01 = fmaf(-2.0f, a01, sq2);
                float v10 = fmaf(-2.0f, a10, sq1);
                float v11 = fmaf(-2.0f, a11, sq2);
                if (ci4[r0] == cl1) mp[r0] = fmaxf(mp[r0], v00); else mn[r0] = fminf(mn[r0], v00);
                if (ci4[r0] == cl2) mp[r0] = fmaxf(mp[r0], v01); else mn[r0] = fminf(mn[r0], v01);
                if (ci4[r1] == cl1) mp[r1] = fmaxf(mp[r1], v10); else mn[r1] = fminf(mn[r1], v10);
                if (ci4[r1] == cl2) mp[r1] = fmaxf(mp[r1], v11); else mn[r1] = fminf(mn[r1], v11);
                if (do_T) {
                    float w00 = fmaf(-2.0f, a00, sqi4[r0]);
                    float w01 = fmaf(-2.0f, a01, sqi4[r0]);
                    float w10 = fmaf(-2.0f, a10, sqi4[r1]);
                    float w11 = fmaf(-2.0f, a11, sqi4[r1]);
                    if (ci4[r0] == cl1) tp0 = fmaxf(tp0, w00); else tq0 = fminf(tq0, w00);
                    if (ci4[r0] == cl2) tp1 = fmaxf(tp1, w01); else tq1 = fminf(tq1, w01);
                    if (ci4[r1] == cl1) tp0 = fmaxf(tp0, w10); else tq0 = fminf(tq0, w10);
                    if (ci4[r1] == cl2) tp1 = fmaxf(tp1, w11); else tq1 = fminf(tq1, w11);
                }
            }
            if (do_T) {
                #pragma unroll
                for (int o = 4; o <= 16; o <<= 1) {
                    tp0 = fmaxf(tp0, __shfl_xor_sync(0xffffffffu, tp0, o));
                    tq0 = fminf(tq0, __shfl_xor_sync(0xffffffffu, tq0, o));
                    tp1 = fmaxf(tp1, __shfl_xor_sync(0xffffffffu, tp1, o));
                    tq1 = fminf(tq1, __shfl_xor_sync(0xffffffffu, tq1, o));
                }
                if (g == 0) {
                    atomicMax(&g_hp[j0 + cc],     enc_f(tp0));
                    atomicMin(&g_hn[j0 + cc],     enc_f(tq0));
                    atomicMax(&g_hp[j0 + cc + 1], enc_f(tp1));
                    atomicMin(&g_hn[j0 + cc + 1], enc_f(tq1));
                }
            }
        }

        #pragma unroll
        for (int r = 0; r < 4; r++) {
            float p = mp[r], q = mn[r];
            #pragma unroll
            for (int o = 2; o; o >>= 1) {
                p = fmaxf(p, __shfl_xor_sync(0xffffffffu, p, o));
                q = fminf(q, __shfl_xor_sync(0xffffffffu, q, o));
            }
            if (t == 0) {
                int i = i0 + wm * 32 + (r >> 1) * 16 + (r & 1) * 8 + g;
                atomicMax(&g_hp[i], enc_f(p));
                atomicMin(&g_hn[i], enc_f(q));
            }
        }
    }
}

// ---------------- kernel 4: loss = sum softplus(hp - hn), 16 blocks ---------
__global__ __launch_bounds__(256) void k_loss(float* __restrict__ out) {
    __shared__ float red[8];
    int i = blockIdx.x * 256 + threadIdx.x;
    float sqi = g_sq[i];
    float hp = sqrtf(fmaxf(sqi + dec_f(g_hp[i]), 0.0f));
    float hn = sqrtf(fmaxf(sqi + dec_f(g_hn[i]), 0.0f));
    float xv = hp - hn;
    float s  = (xv > 20.0f) ? xv : log1pf(expf(xv));
    #pragma unroll
    for (int o = 16; o; o >>= 1) s += __shfl_xor_sync(0xffffffffu, s, o);
    if ((threadIdx.x & 31) == 0) red[threadIdx.x >> 5] = s;
    __syncthreads();
    if (threadIdx.x < 32) {
        float v = (threadIdx.x < 8) ? red[threadIdx.x] : 0.0f;
        #pragma unroll
        for (int o = 4; o; o >>= 1) v += __shfl_xor_sync(0xffffffffu, v, o);
        if (threadIdx.x == 0) atomicAdd(out, v);
    }
}

// ---------------- launch ----------------------------------------------------
extern "C" void kernel_launch(void* const* d_in, const int* in_sizes, int n_in,
                              void* d_out, int out_size) {
    const float* x  = (const float*)d_in[0];
    const float* W  = (const float*)d_in[1];
    const float* b  = (const float*)d_in[2];
    const void*  tg = d_in[3];

    cudaFuncSetAttribute(k_fc,   cudaFuncAttributeMaxDynamicSharedMemorySize, FC_SMEM);
    cudaFuncSetAttribute(k_dist, cudaFuncAttributeMaxDynamicSharedMemorySize, D_SMEM);

    k_init<<<1, 1024>>>((const unsigned*)tg, (float*)d_out);
    k_fc  <<<dim3(D_OUT / 64, N_SAMPLES / 128), 256, FC_SMEM>>>(x, W, b);
    k_dist<<<264, 256, D_SMEM>>>(tg);
    k_loss<<<N_SAMPLES / 256, 256>>>((float*)d_out);
}